// round 1
// baseline (speedup 1.0000x reference)
#include <cuda_runtime.h>
#include <math.h>

// Problem constants (fixed by reference)
#define L_SEQ  2048
#define NFEAT  1024
#define NHEAD  16
#define DHEAD  64
#define BATCH  2
#define MTOT   (BATCH * L_SEQ)   // 4096 rows

// ---------------------------------------------------------------------------
// Device scratch (static globals — no allocation allowed in kernel_launch)
// ---------------------------------------------------------------------------
__device__ float g_C [NFEAT * NFEAT];   // IFFT-real cosine matrix (symmetric)
__device__ float g_Xf[MTOT * NFEAT];    // X @ C
__device__ float g_Q [MTOT * NFEAT];
__device__ float g_K [MTOT * NFEAT];
__device__ float g_V [MTOT * NFEAT];
__device__ float g_A [MTOT * NFEAT];    // attention output (pre out-proj)

// ---------------------------------------------------------------------------
// C[k][n] = cos(2*pi*k*n/1024) / 1024
// Exact angle reduction: k*n mod 1024 (period of the twiddle) keeps the cosf
// argument < 2*pi, so no large-argument precision loss.
// ---------------------------------------------------------------------------
__global__ void gen_cos_kernel() {
    int idx = blockIdx.x * blockDim.x + threadIdx.x;   // 0 .. 1M-1
    int k = idx >> 10;
    int n = idx & 1023;
    int kn = (k * n) & 1023;
    g_C[idx] = cosf((float)kn * 6.135923151542565e-3f) * 9.765625e-4f;
}

// ---------------------------------------------------------------------------
// NT GEMM: Out[M,N] = A[M,K] @ B[N,K]^T + bias[N]
//  - A row-major [M,K], B row-major [N,K] (so Out = A @ B^T)
//  - 128x128 block tile, BK=16, 256 threads, 8x8 register tile per thread
//  - M,N multiples of 128; K multiple of 16 (guaranteed by problem shapes)
// ---------------------------------------------------------------------------
__global__ __launch_bounds__(256) void gemm_nt_kernel(
    const float* __restrict__ A, const float* __restrict__ B,
    const float* __restrict__ bias, float* __restrict__ Out,
    int M, int N, int K)
{
    __shared__ float As[16][129];   // [k][row], +1 pad
    __shared__ float Bs[16][129];   // [k][col], +1 pad

    const int tid = threadIdx.x;
    const int tx = tid & 15;        // 0..15 -> output cols
    const int ty = tid >> 4;        // 0..15 -> output rows
    const int bx = blockIdx.x;      // N tile
    const int by = blockIdx.y;      // M tile

    const float* Ab = A + (size_t)by * 128 * K;
    const float* Bb = B + (size_t)bx * 128 * K;

    float acc[8][8];
    #pragma unroll
    for (int i = 0; i < 8; i++)
        #pragma unroll
        for (int j = 0; j < 8; j++) acc[i][j] = 0.f;

    for (int k0 = 0; k0 < K; k0 += 16) {
        // cooperative load: 128x16 tile each for A and B (8 elems/thread each)
        #pragma unroll
        for (int s = 0; s < 8; s++) {
            int idx = tid + s * 256;       // 0..2047
            int r   = idx >> 4;            // 0..127
            int kk  = idx & 15;            // 0..15
            As[kk][r] = Ab[(size_t)r * K + k0 + kk];
            Bs[kk][r] = Bb[(size_t)r * K + k0 + kk];
        }
        __syncthreads();

        #pragma unroll
        for (int kk = 0; kk < 16; kk++) {
            float a[8], b[8];
            #pragma unroll
            for (int i = 0; i < 4; i++) {
                a[i]     = As[kk][ty * 4 + i];
                a[i + 4] = As[kk][64 + ty * 4 + i];
                b[i]     = Bs[kk][tx * 4 + i];
                b[i + 4] = Bs[kk][64 + tx * 4 + i];
            }
            #pragma unroll
            for (int i = 0; i < 8; i++)
                #pragma unroll
                for (int j = 0; j < 8; j++)
                    acc[i][j] += a[i] * b[j];
        }
        __syncthreads();
    }

    // write out (+ optional bias)
    #pragma unroll
    for (int i = 0; i < 8; i++) {
        int r = by * 128 + ((i < 4) ? (ty * 4 + i) : (64 + ty * 4 + i - 4));
        #pragma unroll
        for (int j = 0; j < 8; j++) {
            int c = bx * 128 + ((j < 4) ? (tx * 4 + j) : (64 + tx * 4 + j - 4));
            float v = acc[i][j];
            if (bias) v += bias[c];
            Out[(size_t)r * N + c] = v;
        }
    }
}

// ---------------------------------------------------------------------------
// Causal flash attention, fp32.
//  grid.x = query tile (32 tiles of 64), grid.y = b*16 + h (32)
//  256 threads; each thread owns a 4x4 patch of the 64x64 tile.
//  scores = Q.K^T / sqrt(1024); causal mask; online softmax; O = P.V
// ---------------------------------------------------------------------------
__global__ __launch_bounds__(256) void attn_kernel(
    const float* __restrict__ Q, const float* __restrict__ K,
    const float* __restrict__ V, float* __restrict__ O)
{
    extern __shared__ float sm[];
    float* Qt = sm;                 // [64 d][65]  Qt[d*65 + qrow]  (transposed)
    float* Kt = Qt + 64 * 65;       // [64 d][65]  Kt[d*65 + krow]  (transposed)
    float* Vs = Kt + 64 * 65;       // [64 kv][65] Vs[krow*65 + d]
    float* Ps = Vs + 64 * 65;       // [64 q][65]  Ps[qrow*65 + kcol]

    const int tid = threadIdx.x;
    const int tx = tid & 15;
    const int ty = tid >> 4;
    const int qt = blockIdx.x;
    const int bh = blockIdx.y;
    const int b  = bh >> 4;
    const int h  = bh & 15;
    const int q0 = qt * 64;
    const size_t rowBase = (size_t)b * L_SEQ;
    const int colBase = h * DHEAD;

    // load Q tile transposed (coalesced global reads, conflict-free smem writes)
    #pragma unroll
    for (int s = 0; s < 16; s++) {
        int idx = tid + s * 256;   // 0..4095
        int r = idx >> 6;          // 0..63
        int d = idx & 63;
        Qt[d * 65 + r] = Q[(rowBase + q0 + r) * NFEAT + colBase + d];
    }

    float m[4], l[4], acc[4][4];
    #pragma unroll
    for (int i = 0; i < 4; i++) {
        m[i] = -INFINITY; l[i] = 0.f;
        #pragma unroll
        for (int j = 0; j < 4; j++) acc[i][j] = 0.f;
    }

    const float inv_scale = 0.03125f;   // 1/sqrt(1024)

    for (int j0 = 0; j0 <= q0; j0 += 64) {
        __syncthreads();   // protect smem from previous iter readers (and Qt load)
        #pragma unroll
        for (int s = 0; s < 16; s++) {
            int idx = tid + s * 256;
            int r = idx >> 6;
            int d = idx & 63;
            float kv = K[(rowBase + j0 + r) * NFEAT + colBase + d];
            float vv = V[(rowBase + j0 + r) * NFEAT + colBase + d];
            Kt[d * 65 + r]  = kv;
            Vs[r * 65 + d]  = vv;
        }
        __syncthreads();

        // S = Q . K^T for this thread's 4x4 patch
        float s4[4][4];
        #pragma unroll
        for (int i = 0; i < 4; i++)
            #pragma unroll
            for (int j = 0; j < 4; j++) s4[i][j] = 0.f;

        #pragma unroll 8
        for (int kk = 0; kk < 64; kk++) {
            float a[4], bb[4];
            #pragma unroll
            for (int i = 0; i < 4; i++) a[i]  = Qt[kk * 65 + ty * 4 + i];
            #pragma unroll
            for (int j = 0; j < 4; j++) bb[j] = Kt[kk * 65 + tx * 4 + j];
            #pragma unroll
            for (int i = 0; i < 4; i++)
                #pragma unroll
                for (int j = 0; j < 4; j++)
                    s4[i][j] += a[i] * bb[j];
        }

        const bool diag = (j0 == q0);   // only diagonal tile needs masking
        #pragma unroll
        for (int i = 0; i < 4; i++) {
            int qi = q0 + ty * 4 + i;
            #pragma unroll
            for (int j = 0; j < 4; j++) {
                float v = s4[i][j] * inv_scale;
                if (diag && (j0 + tx * 4 + j) > qi) v = -INFINITY;
                s4[i][j] = v;
            }
        }

        // online softmax per row (row = 16 tx lanes within a half-warp)
        #pragma unroll
        for (int i = 0; i < 4; i++) {
            float mx = fmaxf(fmaxf(s4[i][0], s4[i][1]), fmaxf(s4[i][2], s4[i][3]));
            #pragma unroll
            for (int off = 8; off > 0; off >>= 1)
                mx = fmaxf(mx, __shfl_xor_sync(0xffffffffu, mx, off, 16));
            float nm = fmaxf(m[i], mx);
            float alpha = __expf(m[i] - nm);   // m=-inf -> alpha=0 on first tile
            float rs = 0.f;
            #pragma unroll
            for (int j = 0; j < 4; j++) {
                float p = __expf(s4[i][j] - nm);
                Ps[(ty * 4 + i) * 65 + tx * 4 + j] = p;
                rs += p;
            }
            #pragma unroll
            for (int off = 8; off > 0; off >>= 1)
                rs += __shfl_xor_sync(0xffffffffu, rs, off, 16);
            l[i] = l[i] * alpha + rs;
            m[i] = nm;
            #pragma unroll
            for (int j = 0; j < 4; j++) acc[i][j] *= alpha;
        }
        __syncthreads();

        // O += P . V
        #pragma unroll 4
        for (int jj = 0; jj < 64; jj++) {
            float a[4], bb[4];
            #pragma unroll
            for (int i = 0; i < 4; i++) a[i]  = Ps[(ty * 4 + i) * 65 + jj];
            #pragma unroll
            for (int j = 0; j < 4; j++) bb[j] = Vs[jj * 65 + tx * 4 + j];
            #pragma unroll
            for (int i = 0; i < 4; i++)
                #pragma unroll
                for (int j = 0; j < 4; j++)
                    acc[i][j] += a[i] * bb[j];
        }
    }

    // normalize + write
    #pragma unroll
    for (int i = 0; i < 4; i++) {
        float inv = 1.f / l[i];
        size_t r = rowBase + q0 + ty * 4 + i;
        #pragma unroll
        for (int j = 0; j < 4; j++)
            O[r * NFEAT + colBase + tx * 4 + j] = acc[i][j] * inv;
    }
}

// ---------------------------------------------------------------------------
// Launch: X -> Xf=X@C -> Q/K/V -> attention -> out-proj
// Inputs (metadata order): X, Wq, bq, Wk, bk, Wv, bv, Wo, bo
// ---------------------------------------------------------------------------
extern "C" void kernel_launch(void* const* d_in, const int* in_sizes, int n_in,
                              void* d_out, int out_size)
{
    const float* X  = (const float*)d_in[0];
    const float* Wq = (const float*)d_in[1];
    const float* bq = (const float*)d_in[2];
    const float* Wk = (const float*)d_in[3];
    const float* bk = (const float*)d_in[4];
    const float* Wv = (const float*)d_in[5];
    const float* bv = (const float*)d_in[6];
    const float* Wo = (const float*)d_in[7];
    const float* bo = (const float*)d_in[8];
    float* out = (float*)d_out;

    float *pC, *pXf, *pQ, *pK, *pV, *pA;
    cudaGetSymbolAddress((void**)&pC,  g_C);
    cudaGetSymbolAddress((void**)&pXf, g_Xf);
    cudaGetSymbolAddress((void**)&pQ,  g_Q);
    cudaGetSymbolAddress((void**)&pK,  g_K);
    cudaGetSymbolAddress((void**)&pV,  g_V);
    cudaGetSymbolAddress((void**)&pA,  g_A);

    const int ATTN_SMEM = 4 * 64 * 65 * (int)sizeof(float);   // 66560 B
    cudaFuncSetAttribute(attn_kernel,
                         cudaFuncAttributeMaxDynamicSharedMemorySize, ATTN_SMEM);

    // 1) cosine matrix for IFFT-real (1M elems)
    gen_cos_kernel<<<(NFEAT * NFEAT) / 256, 256>>>();

    dim3 gproj(NFEAT / 128, MTOT / 128);   // (8, 32)
    dim3 blk(256);

    // 2) Xf = X @ C   (C symmetric -> NT form works with B = C)
    gemm_nt_kernel<<<gproj, blk>>>(X, pC, nullptr, pXf, MTOT, NFEAT, NFEAT);

    // 3) projections: Q/K/V = Xf @ W^T + b
    gemm_nt_kernel<<<gproj, blk>>>(pXf, Wq, bq, pQ, MTOT, NFEAT, NFEAT);
    gemm_nt_kernel<<<gproj, blk>>>(pXf, Wk, bk, pK, MTOT, NFEAT, NFEAT);
    gemm_nt_kernel<<<gproj, blk>>>(pXf, Wv, bv, pV, MTOT, NFEAT, NFEAT);

    // 4) causal multi-head attention
    attn_kernel<<<dim3(L_SEQ / 64, BATCH * NHEAD), blk, ATTN_SMEM>>>(pQ, pK, pV, pA);

    // 5) output projection -> d_out
    gemm_nt_kernel<<<gproj, blk>>>(pA, Wo, bo, out, MTOT, NFEAT, NFEAT);
}

// round 3
// speedup vs baseline: 2.0085x; 2.0085x over previous
#include <cuda_runtime.h>
#include <cuda_bf16.h>
#include <math.h>
#include <stdint.h>

// Problem constants
#define L_SEQ  2048
#define NFEAT  1024
#define NHEAD  16
#define DHEAD  64
#define BATCH  2
#define MTOT   (BATCH * L_SEQ)   // 4096

// ---------------------------------------------------------------------------
// Helpers
// ---------------------------------------------------------------------------
__device__ __forceinline__ uint32_t smem_u32(const void* p) {
    uint32_t a;
    asm("{ .reg .u64 t; cvta.to.shared.u64 t, %1; cvt.u32.u64 %0, t; }" : "=r"(a) : "l"(p));
    return a;
}

#define CP_ASYNC16(dst, src) \
    asm volatile("cp.async.cg.shared.global [%0], [%1], 16;" :: "r"(dst), "l"(src))
#define CP_COMMIT()  asm volatile("cp.async.commit_group;" ::: "memory")
#define CP_WAIT(n)   asm volatile("cp.async.wait_group %0;" :: "n"(n) : "memory")

__device__ __forceinline__ void ldmx4(uint32_t (&r)[4], uint32_t addr) {
    asm volatile("ldmatrix.sync.aligned.m8n8.x4.shared.b16 {%0,%1,%2,%3}, [%4];"
        : "=r"(r[0]), "=r"(r[1]), "=r"(r[2]), "=r"(r[3]) : "r"(addr));
}

__device__ __forceinline__ void mma16816(float (&d)[4], const uint32_t (&a)[4],
                                         uint32_t b0, uint32_t b1) {
    asm volatile("mma.sync.aligned.m16n8k16.row.col.f32.bf16.bf16.f32 "
        "{%0,%1,%2,%3}, {%4,%5,%6,%7}, {%8,%9}, {%0,%1,%2,%3};"
        : "+f"(d[0]), "+f"(d[1]), "+f"(d[2]), "+f"(d[3])
        : "r"(a[0]), "r"(a[1]), "r"(a[2]), "r"(a[3]), "r"(b0), "r"(b1));
}

// ---------------------------------------------------------------------------
// Device scratch
// ---------------------------------------------------------------------------
__device__ __nv_bfloat16 g_Ch [NFEAT * NFEAT], g_Cl [NFEAT * NFEAT];
__device__ __nv_bfloat16 g_Xh [MTOT * NFEAT],  g_Xl [MTOT * NFEAT];
__device__ __nv_bfloat16 g_WqH[NFEAT * NFEAT], g_WqL[NFEAT * NFEAT];
__device__ __nv_bfloat16 g_WkH[NFEAT * NFEAT], g_WkL[NFEAT * NFEAT];
__device__ __nv_bfloat16 g_WvH[NFEAT * NFEAT], g_WvL[NFEAT * NFEAT];
__device__ __nv_bfloat16 g_WoH[NFEAT * NFEAT], g_WoL[NFEAT * NFEAT];
__device__ __nv_bfloat16 g_XfH[MTOT * NFEAT],  g_XfL[MTOT * NFEAT];
__device__ __nv_bfloat16 g_AH [MTOT * NFEAT],  g_AL [MTOT * NFEAT];
__device__ float g_Q[MTOT * NFEAT], g_K[MTOT * NFEAT], g_V[MTOT * NFEAT];

// ---------------------------------------------------------------------------
// C[k][n] = cos(2*pi*k*n/1024)/1024, as bf16 hi/lo split
// ---------------------------------------------------------------------------
__global__ void gen_cos_kernel() {
    int idx = blockIdx.x * blockDim.x + threadIdx.x;
    int k = idx >> 10, n = idx & 1023;
    int kn = (k * n) & 1023;
    float v = cosf((float)kn * 6.135923151542565e-3f) * 9.765625e-4f;
    __nv_bfloat16 h = __float2bfloat16(v);
    g_Ch[idx] = h;
    g_Cl[idx] = __float2bfloat16(v - __bfloat162float(h));
}

__global__ void split_kernel(const float* __restrict__ in,
                             __nv_bfloat16* __restrict__ hi,
                             __nv_bfloat16* __restrict__ lo, int n) {
    int i = blockIdx.x * blockDim.x + threadIdx.x;
    if (i < n) {
        float x = in[i];
        __nv_bfloat16 h = __float2bfloat16(x);
        hi[i] = h;
        lo[i] = __float2bfloat16(x - __bfloat162float(h));
    }
}

// ---------------------------------------------------------------------------
// Split-bf16 NT GEMM on mma.sync (HMMA):
//   Out[4096,1024] = A @ B^T (+bias), A/B given as bf16 hi/lo pairs,
//   D ~= Ah*Bh + Ah*Bl + Al*Bh.
//   128x128 tile, BK=32, 8 warps (64x32 each), double-buffered cp.async.
//   Smem rows: [hi 32bf16 | lo 32bf16] = 128B, chunk-XOR swizzle -> conflict-free.
// ---------------------------------------------------------------------------
#define STAGE_BYTES 32768                      // sA 16KB + sB 16KB
#define GEMM_SMEM   (2 * STAGE_BYTES + 128)

__global__ __launch_bounds__(256, 1) void mma_gemm_kernel(
    const __nv_bfloat16* __restrict__ Ah, const __nv_bfloat16* __restrict__ Al,
    const __nv_bfloat16* __restrict__ Bh, const __nv_bfloat16* __restrict__ Bl,
    const float* __restrict__ bias, float* __restrict__ outF,
    __nv_bfloat16* __restrict__ outH, __nv_bfloat16* __restrict__ outL)
{
    extern __shared__ char sraw[];
    uint32_t base = smem_u32(sraw);
    base = (base + 127) & ~127u;

    const int tid  = threadIdx.x;
    const int lane = tid & 31;
    const int wid  = tid >> 5;
    const int wm   = wid & 1;                  // 2 warp rows (64 each)
    const int wn   = wid >> 1;                 // 4 warp cols (32 each)
    const int bx = blockIdx.x, by = blockIdx.y;

    const size_t aBase = (size_t)by * 128 * 1024;
    const size_t bBase = (size_t)bx * 128 * 1024;

    float acc[4][4][4];
    #pragma unroll
    for (int i = 0; i < 4; i++)
        #pragma unroll
        for (int j = 0; j < 4; j++)
            #pragma unroll
            for (int r = 0; r < 4; r++) acc[i][j][r] = 0.f;

    // stage fill: 2048 16B-chunks (A:1024, B:1024), 8 per thread
    #define ISSUE_STAGE(c) do { \
        const uint32_t sb = base + ((c) & 1) * STAGE_BYTES; \
        const int k0 = (c) * 32; \
        _Pragma("unroll") \
        for (int s = 0; s < 8; s++) { \
            int i  = tid + s * 256; \
            int tl = i >> 10; \
            int j  = i & 1023; \
            int row = j >> 3; \
            int ch  = j & 7; \
            uint32_t dst = sb + (uint32_t)tl * 16384u + (uint32_t)row * 128u \
                         + (uint32_t)((ch ^ (row & 7)) * 16); \
            size_t off = (size_t)row * 1024 + k0 + (ch & 3) * 8; \
            const __nv_bfloat16* src = (tl == 0) \
                ? ((ch < 4 ? Ah : Al) + aBase + off) \
                : ((ch < 4 ? Bh : Bl) + bBase + off); \
            CP_ASYNC16(dst, src); \
        } \
        CP_COMMIT(); \
    } while (0)

    ISSUE_STAGE(0);

    #pragma unroll 1
    for (int c = 0; c < 32; c++) {
        if (c + 1 < 32) { ISSUE_STAGE(c + 1); CP_WAIT(1); }
        else            { CP_WAIT(0); }
        __syncthreads();

        const uint32_t sA = base + (c & 1) * STAGE_BYTES;
        const uint32_t sB = sA + 16384;

        #pragma unroll
        for (int ks = 0; ks < 2; ks++) {
            uint32_t ahf[4][4], alf[4][4], bhf[4][2], blf[4][2];
            // A fragments: 4 m16 tiles x (hi, lo)
            #pragma unroll
            for (int mi = 0; mi < 4; mi++) {
                int row = wm * 64 + mi * 16 + (lane & 15);
                int chH = ks * 2 + (lane >> 4);
                int chL = chH + 4;
                ldmx4(ahf[mi], sA + row * 128 + ((chH ^ (row & 7)) * 16));
                ldmx4(alf[mi], sA + row * 128 + ((chL ^ (row & 7)) * 16));
            }
            // B fragments: 4 n8 tiles packed 2-per-x4, x (hi, lo)
            #pragma unroll
            for (int p = 0; p < 2; p++) {
                int row = wn * 32 + p * 16 + (lane >> 4) * 8 + (lane & 7);
                int chH = ks * 2 + ((lane >> 3) & 1);
                int chL = chH + 4;
                uint32_t th[4], tl4[4];
                ldmx4(th,  sB + row * 128 + ((chH ^ (row & 7)) * 16));
                ldmx4(tl4, sB + row * 128 + ((chL ^ (row & 7)) * 16));
                bhf[2*p][0] = th[0];  bhf[2*p][1] = th[1];
                bhf[2*p+1][0] = th[2]; bhf[2*p+1][1] = th[3];
                blf[2*p][0] = tl4[0]; blf[2*p][1] = tl4[1];
                blf[2*p+1][0] = tl4[2]; blf[2*p+1][1] = tl4[3];
            }
            #pragma unroll
            for (int mi = 0; mi < 4; mi++)
                #pragma unroll
                for (int nj = 0; nj < 4; nj++) {
                    mma16816(acc[mi][nj], ahf[mi], bhf[nj][0], bhf[nj][1]);
                    mma16816(acc[mi][nj], ahf[mi], blf[nj][0], blf[nj][1]);
                    mma16816(acc[mi][nj], alf[mi], bhf[nj][0], bhf[nj][1]);
                }
        }
        __syncthreads();
    }

    // epilogue: d0,d1 -> (row, col..col+1); d2,d3 -> (row+8, col..col+1)
    const int r0 = by * 128 + wm * 64 + (lane >> 2);
    const int c0 = bx * 128 + wn * 32 + (lane & 3) * 2;
    #pragma unroll
    for (int mi = 0; mi < 4; mi++)
        #pragma unroll
        for (int nj = 0; nj < 4; nj++)
            #pragma unroll
            for (int h = 0; h < 2; h++) {
                int r = r0 + mi * 16 + h * 8;
                int cc = c0 + nj * 8;
                float v0 = acc[mi][nj][2*h+0];
                float v1 = acc[mi][nj][2*h+1];
                if (bias) { v0 += bias[cc]; v1 += bias[cc + 1]; }
                size_t o = (size_t)r * 1024 + cc;
                if (outF) *(float2*)(outF + o) = make_float2(v0, v1);
                if (outH) {
                    __nv_bfloat16 h0 = __float2bfloat16(v0);
                    __nv_bfloat16 h1 = __float2bfloat16(v1);
                    __nv_bfloat162 ph; ph.x = h0; ph.y = h1;
                    __nv_bfloat162 pl;
                    pl.x = __float2bfloat16(v0 - __bfloat162float(h0));
                    pl.y = __float2bfloat16(v1 - __bfloat162float(h1));
                    *(__nv_bfloat162*)(outH + o) = ph;
                    *(__nv_bfloat162*)(outL + o) = pl;
                }
            }
}

// ---------------------------------------------------------------------------
// Causal flash attention, fp32 SIMT; emits hi/lo bf16 output.
// ---------------------------------------------------------------------------
__global__ __launch_bounds__(256) void attn_kernel(
    const float* __restrict__ Q, const float* __restrict__ K,
    const float* __restrict__ V,
    __nv_bfloat16* __restrict__ Oh, __nv_bfloat16* __restrict__ Ol)
{
    extern __shared__ float sm[];
    float* Qt = sm;                 // [64 d][65]
    float* Kt = Qt + 64 * 65;
    float* Vs = Kt + 64 * 65;
    float* Ps = Vs + 64 * 65;

    const int tid = threadIdx.x;
    const int tx = tid & 15;
    const int ty = tid >> 4;
    const int q0 = blockIdx.x * 64;
    const int bh = blockIdx.y;
    const size_t rowBase = (size_t)(bh >> 4) * L_SEQ;
    const int colBase = (bh & 15) * DHEAD;

    #pragma unroll
    for (int s = 0; s < 16; s++) {
        int idx = tid + s * 256;
        int r = idx >> 6, d = idx & 63;
        Qt[d * 65 + r] = Q[(rowBase + q0 + r) * NFEAT + colBase + d];
    }

    float m[4], l[4], acc[4][4];
    #pragma unroll
    for (int i = 0; i < 4; i++) {
        m[i] = -INFINITY; l[i] = 0.f;
        #pragma unroll
        for (int j = 0; j < 4; j++) acc[i][j] = 0.f;
    }
    const float inv_scale = 0.03125f;

    for (int j0 = 0; j0 <= q0; j0 += 64) {
        __syncthreads();
        #pragma unroll
        for (int s = 0; s < 16; s++) {
            int idx = tid + s * 256;
            int r = idx >> 6, d = idx & 63;
            Kt[d * 65 + r] = K[(rowBase + j0 + r) * NFEAT + colBase + d];
            Vs[r * 65 + d] = V[(rowBase + j0 + r) * NFEAT + colBase + d];
        }
        __syncthreads();

        float s4[4][4];
        #pragma unroll
        for (int i = 0; i < 4; i++)
            #pragma unroll
            for (int j = 0; j < 4; j++) s4[i][j] = 0.f;

        #pragma unroll 8
        for (int kk = 0; kk < 64; kk++) {
            float a[4], bb[4];
            #pragma unroll
            for (int i = 0; i < 4; i++) a[i]  = Qt[kk * 65 + ty * 4 + i];
            #pragma unroll
            for (int j = 0; j < 4; j++) bb[j] = Kt[kk * 65 + tx * 4 + j];
            #pragma unroll
            for (int i = 0; i < 4; i++)
                #pragma unroll
                for (int j = 0; j < 4; j++) s4[i][j] += a[i] * bb[j];
        }

        const bool diag = (j0 == q0);
        #pragma unroll
        for (int i = 0; i < 4; i++) {
            int qi = q0 + ty * 4 + i;
            #pragma unroll
            for (int j = 0; j < 4; j++) {
                float v = s4[i][j] * inv_scale;
                if (diag && (j0 + tx * 4 + j) > qi) v = -INFINITY;
                s4[i][j] = v;
            }
        }

        #pragma unroll
        for (int i = 0; i < 4; i++) {
            float mx = fmaxf(fmaxf(s4[i][0], s4[i][1]), fmaxf(s4[i][2], s4[i][3]));
            #pragma unroll
            for (int off = 8; off > 0; off >>= 1)
                mx = fmaxf(mx, __shfl_xor_sync(0xffffffffu, mx, off, 16));
            float nm = fmaxf(m[i], mx);
            float alpha = __expf(m[i] - nm);
            float rs = 0.f;
            #pragma unroll
            for (int j = 0; j < 4; j++) {
                float p = __expf(s4[i][j] - nm);
                Ps[(ty * 4 + i) * 65 + tx * 4 + j] = p;
                rs += p;
            }
            #pragma unroll
            for (int off = 8; off > 0; off >>= 1)
                rs += __shfl_xor_sync(0xffffffffu, rs, off, 16);
            l[i] = l[i] * alpha + rs;
            m[i] = nm;
            #pragma unroll
            for (int j = 0; j < 4; j++) acc[i][j] *= alpha;
        }
        __syncthreads();

        #pragma unroll 4
        for (int jj = 0; jj < 64; jj++) {
            float a[4], bb[4];
            #pragma unroll
            for (int i = 0; i < 4; i++) a[i]  = Ps[(ty * 4 + i) * 65 + jj];
            #pragma unroll
            for (int j = 0; j < 4; j++) bb[j] = Vs[jj * 65 + tx * 4 + j];
            #pragma unroll
            for (int i = 0; i < 4; i++)
                #pragma unroll
                for (int j = 0; j < 4; j++) acc[i][j] += a[i] * bb[j];
        }
    }

    #pragma unroll
    for (int i = 0; i < 4; i++) {
        float inv = 1.f / l[i];
        size_t r = rowBase + q0 + ty * 4 + i;
        #pragma unroll
        for (int j = 0; j < 4; j++) {
            float v = acc[i][j] * inv;
            __nv_bfloat16 h = __float2bfloat16(v);
            size_t o = r * NFEAT + colBase + tx * 4 + j;
            Oh[o] = h;
            Ol[o] = __float2bfloat16(v - __bfloat162float(h));
        }
    }
}

// ---------------------------------------------------------------------------
// Launch
// ---------------------------------------------------------------------------
extern "C" void kernel_launch(void* const* d_in, const int* in_sizes, int n_in,
                              void* d_out, int out_size)
{
    const float* X  = (const float*)d_in[0];
    const float* Wq = (const float*)d_in[1];
    const float* bq = (const float*)d_in[2];
    const float* Wk = (const float*)d_in[3];
    const float* bk = (const float*)d_in[4];
    const float* Wv = (const float*)d_in[5];
    const float* bv = (const float*)d_in[6];
    const float* Wo = (const float*)d_in[7];
    const float* bo = (const float*)d_in[8];
    float* out = (float*)d_out;

    __nv_bfloat16 *Ch, *Cl, *Xh, *Xl, *WqH, *WqL, *WkH, *WkL, *WvH, *WvL, *WoH, *WoL;
    __nv_bfloat16 *XfH, *XfL, *AH, *AL;
    float *Qf, *Kf, *Vf;
    cudaGetSymbolAddress((void**)&Ch,  g_Ch);  cudaGetSymbolAddress((void**)&Cl,  g_Cl);
    cudaGetSymbolAddress((void**)&Xh,  g_Xh);  cudaGetSymbolAddress((void**)&Xl,  g_Xl);
    cudaGetSymbolAddress((void**)&WqH, g_WqH); cudaGetSymbolAddress((void**)&WqL, g_WqL);
    cudaGetSymbolAddress((void**)&WkH, g_WkH); cudaGetSymbolAddress((void**)&WkL, g_WkL);
    cudaGetSymbolAddress((void**)&WvH, g_WvH); cudaGetSymbolAddress((void**)&WvL, g_WvL);
    cudaGetSymbolAddress((void**)&WoH, g_WoH); cudaGetSymbolAddress((void**)&WoL, g_WoL);
    cudaGetSymbolAddress((void**)&XfH, g_XfH); cudaGetSymbolAddress((void**)&XfL, g_XfL);
    cudaGetSymbolAddress((void**)&AH,  g_AH);  cudaGetSymbolAddress((void**)&AL,  g_AL);
    cudaGetSymbolAddress((void**)&Qf,  g_Q);
    cudaGetSymbolAddress((void**)&Kf,  g_K);
    cudaGetSymbolAddress((void**)&Vf,  g_V);

    const int ATTN_SMEM = 4 * 64 * 65 * (int)sizeof(float);
    cudaFuncSetAttribute(attn_kernel,
                         cudaFuncAttributeMaxDynamicSharedMemorySize, ATTN_SMEM);
    cudaFuncSetAttribute(mma_gemm_kernel,
                         cudaFuncAttributeMaxDynamicSharedMemorySize, GEMM_SMEM);

    // 1) cosine matrix (bf16 hi/lo)
    gen_cos_kernel<<<(NFEAT * NFEAT) / 256, 256>>>();

    // 2) split inputs to bf16 hi/lo
    split_kernel<<<(MTOT * NFEAT) / 256, 256>>>(X, Xh, Xl, MTOT * NFEAT);
    split_kernel<<<(NFEAT * NFEAT) / 256, 256>>>(Wq, WqH, WqL, NFEAT * NFEAT);
    split_kernel<<<(NFEAT * NFEAT) / 256, 256>>>(Wk, WkH, WkL, NFEAT * NFEAT);
    split_kernel<<<(NFEAT * NFEAT) / 256, 256>>>(Wv, WvH, WvL, NFEAT * NFEAT);
    split_kernel<<<(NFEAT * NFEAT) / 256, 256>>>(Wo, WoH, WoL, NFEAT * NFEAT);

    dim3 gg(NFEAT / 128, MTOT / 128);   // (8, 32)

    // 3) Xf = X @ C (C symmetric) -> hi/lo only
    mma_gemm_kernel<<<gg, 256, GEMM_SMEM>>>(Xh, Xl, Ch, Cl,
                                            nullptr, nullptr, XfH, XfL);
    // 4) Q/K/V = Xf @ W^T + b (fp32 for attention)
    mma_gemm_kernel<<<gg, 256, GEMM_SMEM>>>(XfH, XfL, WqH, WqL, bq, Qf, nullptr, nullptr);
    mma_gemm_kernel<<<gg, 256, GEMM_SMEM>>>(XfH, XfL, WkH, WkL, bk, Kf, nullptr, nullptr);
    mma_gemm_kernel<<<gg, 256, GEMM_SMEM>>>(XfH, XfL, WvH, WvL, bv, Vf, nullptr, nullptr);

    // 5) causal attention -> hi/lo
    attn_kernel<<<dim3(L_SEQ / 64, BATCH * NHEAD), 256, ATTN_SMEM>>>(Qf, Kf, Vf, AH, AL);

    // 6) out = A @ Wo^T + bo
    mma_gemm_kernel<<<gg, 256, GEMM_SMEM>>>(AH, AL, WoH, WoL, bo, out, nullptr, nullptr);
}

// round 4
// speedup vs baseline: 3.7568x; 1.8705x over previous
#include <cuda_runtime.h>
#include <cuda_bf16.h>
#include <math.h>
#include <stdint.h>

// Problem constants
#define L_SEQ  2048
#define NFEAT  1024
#define NHEAD  16
#define DHEAD  64
#define BATCH  2
#define MTOT   (BATCH * L_SEQ)   // 4096

// ---------------------------------------------------------------------------
// Helpers
// ---------------------------------------------------------------------------
__device__ __forceinline__ uint32_t smem_u32(const void* p) {
    uint32_t a;
    asm("{ .reg .u64 t; cvta.to.shared.u64 t, %1; cvt.u32.u64 %0, t; }" : "=r"(a) : "l"(p));
    return a;
}

#define CP_ASYNC16(dst, src) \
    asm volatile("cp.async.cg.shared.global [%0], [%1], 16;" :: "r"(dst), "l"(src))
#define CP_COMMIT()  asm volatile("cp.async.commit_group;" ::: "memory")
#define CP_WAIT(n)   asm volatile("cp.async.wait_group %0;" :: "n"(n) : "memory")

__device__ __forceinline__ void ldmx4(uint32_t (&r)[4], uint32_t addr) {
    asm volatile("ldmatrix.sync.aligned.m8n8.x4.shared.b16 {%0,%1,%2,%3}, [%4];"
        : "=r"(r[0]), "=r"(r[1]), "=r"(r[2]), "=r"(r[3]) : "r"(addr));
}
__device__ __forceinline__ void ldmx4t(uint32_t (&r)[4], uint32_t addr) {
    asm volatile("ldmatrix.sync.aligned.m8n8.x4.trans.shared.b16 {%0,%1,%2,%3}, [%4];"
        : "=r"(r[0]), "=r"(r[1]), "=r"(r[2]), "=r"(r[3]) : "r"(addr));
}

__device__ __forceinline__ void mma16816(float (&d)[4], const uint32_t (&a)[4],
                                         uint32_t b0, uint32_t b1) {
    asm volatile("mma.sync.aligned.m16n8k16.row.col.f32.bf16.bf16.f32 "
        "{%0,%1,%2,%3}, {%4,%5,%6,%7}, {%8,%9}, {%0,%1,%2,%3};"
        : "+f"(d[0]), "+f"(d[1]), "+f"(d[2]), "+f"(d[3])
        : "r"(a[0]), "r"(a[1]), "r"(a[2]), "r"(a[3]), "r"(b0), "r"(b1));
}

// split (x,y) fp32 pair into packed bf16x2 hi + bf16x2 lo residual
__device__ __forceinline__ void split2(float x, float y, uint32_t& h, uint32_t& l) {
    __nv_bfloat16 hx = __float2bfloat16(x), hy = __float2bfloat16(y);
    __nv_bfloat162 hh; hh.x = hx; hh.y = hy;
    __nv_bfloat162 ll;
    ll.x = __float2bfloat16(x - __bfloat162float(hx));
    ll.y = __float2bfloat16(y - __bfloat162float(hy));
    h = *reinterpret_cast<uint32_t*>(&hh);
    l = *reinterpret_cast<uint32_t*>(&ll);
}

// ---------------------------------------------------------------------------
// Device scratch
// ---------------------------------------------------------------------------
__device__ __nv_bfloat16 g_Ch [NFEAT * NFEAT], g_Cl [NFEAT * NFEAT];
__device__ __nv_bfloat16 g_Xh [MTOT * NFEAT],  g_Xl [MTOT * NFEAT];
__device__ __nv_bfloat16 g_WqH[NFEAT * NFEAT], g_WqL[NFEAT * NFEAT];
__device__ __nv_bfloat16 g_WkH[NFEAT * NFEAT], g_WkL[NFEAT * NFEAT];
__device__ __nv_bfloat16 g_WvH[NFEAT * NFEAT], g_WvL[NFEAT * NFEAT];
__device__ __nv_bfloat16 g_WoH[NFEAT * NFEAT], g_WoL[NFEAT * NFEAT];
__device__ __nv_bfloat16 g_XfH[MTOT * NFEAT],  g_XfL[MTOT * NFEAT];
__device__ __nv_bfloat16 g_QH [MTOT * NFEAT],  g_QL [MTOT * NFEAT];
__device__ __nv_bfloat16 g_KH [MTOT * NFEAT],  g_KL [MTOT * NFEAT];
__device__ __nv_bfloat16 g_VH [MTOT * NFEAT],  g_VL [MTOT * NFEAT];
__device__ __nv_bfloat16 g_AH [MTOT * NFEAT],  g_AL [MTOT * NFEAT];

// ---------------------------------------------------------------------------
// C[k][n] = cos(2*pi*k*n/1024)/1024, as bf16 hi/lo split
// ---------------------------------------------------------------------------
__global__ void gen_cos_kernel() {
    int idx = blockIdx.x * blockDim.x + threadIdx.x;
    int k = idx >> 10, n = idx & 1023;
    int kn = (k * n) & 1023;
    float v = cosf((float)kn * 6.135923151542565e-3f) * 9.765625e-4f;
    __nv_bfloat16 h = __float2bfloat16(v);
    g_Ch[idx] = h;
    g_Cl[idx] = __float2bfloat16(v - __bfloat162float(h));
}

__global__ void split_kernel(const float* __restrict__ in,
                             __nv_bfloat16* __restrict__ hi,
                             __nv_bfloat16* __restrict__ lo, int n) {
    int i = blockIdx.x * blockDim.x + threadIdx.x;
    if (i < n) {
        float x = in[i];
        __nv_bfloat16 h = __float2bfloat16(x);
        hi[i] = h;
        lo[i] = __float2bfloat16(x - __bfloat162float(h));
    }
}

// ---------------------------------------------------------------------------
// Split-bf16 NT GEMM on mma.sync (HMMA), 3-stage cp.async pipeline.
//   Out[4096,1024] = A @ B^T (+bias), D ~= Ah*Bh + Ah*Bl + Al*Bh.
//   128x128 tile, BK=32, 8 warps (64x32 each).
//   Smem rows: [hi 32bf16 | lo 32bf16] = 128B, chunk-XOR swizzle.
// ---------------------------------------------------------------------------
#define STAGE_BYTES 32768                      // sA 16KB + sB 16KB
#define GEMM_STAGES 3
#define GEMM_SMEM   (GEMM_STAGES * STAGE_BYTES + 128)

__global__ __launch_bounds__(256, 1) void mma_gemm_kernel(
    const __nv_bfloat16* __restrict__ Ah, const __nv_bfloat16* __restrict__ Al,
    const __nv_bfloat16* __restrict__ Bh, const __nv_bfloat16* __restrict__ Bl,
    const float* __restrict__ bias, float* __restrict__ outF,
    __nv_bfloat16* __restrict__ outH, __nv_bfloat16* __restrict__ outL)
{
    extern __shared__ char sraw[];
    uint32_t base = smem_u32(sraw);
    base = (base + 127) & ~127u;

    const int tid  = threadIdx.x;
    const int lane = tid & 31;
    const int wid  = tid >> 5;
    const int wm   = wid & 1;                  // 2 warp rows (64 each)
    const int wn   = wid >> 1;                 // 4 warp cols (32 each)
    const int bx = blockIdx.x, by = blockIdx.y;

    const size_t aBase = (size_t)by * 128 * 1024;
    const size_t bBase = (size_t)bx * 128 * 1024;

    float acc[4][4][4];
    #pragma unroll
    for (int i = 0; i < 4; i++)
        #pragma unroll
        for (int j = 0; j < 4; j++)
            #pragma unroll
            for (int r = 0; r < 4; r++) acc[i][j][r] = 0.f;

    #define ISSUE_STAGE(c) do { \
        const uint32_t sb = base + ((c) % GEMM_STAGES) * STAGE_BYTES; \
        const int k0 = (c) * 32; \
        _Pragma("unroll") \
        for (int s = 0; s < 8; s++) { \
            int i  = tid + s * 256; \
            int tl = i >> 10; \
            int j  = i & 1023; \
            int row = j >> 3; \
            int ch  = j & 7; \
            uint32_t dst = sb + (uint32_t)tl * 16384u + (uint32_t)row * 128u \
                         + (uint32_t)((ch ^ (row & 7)) * 16); \
            size_t off = (size_t)row * 1024 + k0 + (ch & 3) * 8; \
            const __nv_bfloat16* src = (tl == 0) \
                ? ((ch < 4 ? Ah : Al) + aBase + off) \
                : ((ch < 4 ? Bh : Bl) + bBase + off); \
            CP_ASYNC16(dst, src); \
        } \
        CP_COMMIT(); \
    } while (0)

    ISSUE_STAGE(0);
    ISSUE_STAGE(1);

    #pragma unroll 1
    for (int c = 0; c < 32; c++) {
        __syncthreads();                       // all warps done reading buf (c-1)%3
        if (c + 2 < 32) { ISSUE_STAGE(c + 2); CP_WAIT(2); }
        else if (c + 1 < 32) { CP_WAIT(1); }
        else { CP_WAIT(0); }
        __syncthreads();                       // stage c visible to all

        const uint32_t sA = base + (c % GEMM_STAGES) * STAGE_BYTES;
        const uint32_t sB = sA + 16384;

        #pragma unroll
        for (int ks = 0; ks < 2; ks++) {
            uint32_t ahf[4][4], alf[4][4], bhf[4][2], blf[4][2];
            #pragma unroll
            for (int mi = 0; mi < 4; mi++) {
                int row = wm * 64 + mi * 16 + (lane & 15);
                int chH = ks * 2 + (lane >> 4);
                int chL = chH + 4;
                ldmx4(ahf[mi], sA + row * 128 + ((chH ^ (row & 7)) * 16));
                ldmx4(alf[mi], sA + row * 128 + ((chL ^ (row & 7)) * 16));
            }
            #pragma unroll
            for (int p = 0; p < 2; p++) {
                int row = wn * 32 + p * 16 + (lane >> 4) * 8 + (lane & 7);
                int chH = ks * 2 + ((lane >> 3) & 1);
                int chL = chH + 4;
                uint32_t th[4], tl4[4];
                ldmx4(th,  sB + row * 128 + ((chH ^ (row & 7)) * 16));
                ldmx4(tl4, sB + row * 128 + ((chL ^ (row & 7)) * 16));
                bhf[2*p][0] = th[0];   bhf[2*p][1] = th[1];
                bhf[2*p+1][0] = th[2]; bhf[2*p+1][1] = th[3];
                blf[2*p][0] = tl4[0];  blf[2*p][1] = tl4[1];
                blf[2*p+1][0] = tl4[2]; blf[2*p+1][1] = tl4[3];
            }
            #pragma unroll
            for (int mi = 0; mi < 4; mi++)
                #pragma unroll
                for (int nj = 0; nj < 4; nj++) {
                    mma16816(acc[mi][nj], ahf[mi], bhf[nj][0], bhf[nj][1]);
                    mma16816(acc[mi][nj], ahf[mi], blf[nj][0], blf[nj][1]);
                    mma16816(acc[mi][nj], alf[mi], bhf[nj][0], bhf[nj][1]);
                }
        }
    }

    const int r0 = by * 128 + wm * 64 + (lane >> 2);
    const int c0 = bx * 128 + wn * 32 + (lane & 3) * 2;
    #pragma unroll
    for (int mi = 0; mi < 4; mi++)
        #pragma unroll
        for (int nj = 0; nj < 4; nj++)
            #pragma unroll
            for (int h = 0; h < 2; h++) {
                int r = r0 + mi * 16 + h * 8;
                int cc = c0 + nj * 8;
                float v0 = acc[mi][nj][2*h+0];
                float v1 = acc[mi][nj][2*h+1];
                if (bias) { v0 += bias[cc]; v1 += bias[cc + 1]; }
                size_t o = (size_t)r * 1024 + cc;
                if (outF) *(float2*)(outF + o) = make_float2(v0, v1);
                if (outH) {
                    uint32_t ph, pl;
                    split2(v0, v1, ph, pl);
                    *(uint32_t*)(outH + o) = ph;
                    *(uint32_t*)(outL + o) = pl;
                }
            }
}

// ---------------------------------------------------------------------------
// Tensor-core causal flash attention, split-bf16 (3-term) QK^T and PV.
//  Q tile 64 x d64, KV tiles 64, 4 warps (one m16 slab each), 128 threads.
//  Q/K/V given as bf16 hi/lo; output written as bf16 hi/lo for the out-proj.
//  Smem: Qh/Ql (16KB) + 2 KV stages (Kh,Kl,Vh,Vl = 32KB each).
// ---------------------------------------------------------------------------
#define ATTN_SMEM (16384 + 2 * 32768 + 128)

__global__ __launch_bounds__(128, 2) void attn_mma_kernel(
    const __nv_bfloat16* __restrict__ Qh_g, const __nv_bfloat16* __restrict__ Ql_g,
    const __nv_bfloat16* __restrict__ Kh_g, const __nv_bfloat16* __restrict__ Kl_g,
    const __nv_bfloat16* __restrict__ Vh_g, const __nv_bfloat16* __restrict__ Vl_g,
    __nv_bfloat16* __restrict__ Oh, __nv_bfloat16* __restrict__ Ol)
{
    extern __shared__ char sraw[];
    uint32_t base = smem_u32(sraw);
    base = (base + 127) & ~127u;

    const int tid  = threadIdx.x;
    const int lane = tid & 31;
    const int wm   = tid >> 5;                 // warp 0..3 -> q rows wm*16..
    const int qt   = blockIdx.x;
    const int q0   = qt * 64;
    const int bh   = blockIdx.y;
    const size_t rowBase = (size_t)(bh >> 4) * L_SEQ;
    const int colBase = (bh & 15) * DHEAD;
    const int T = qt + 1;                      // KV tiles (causal)

    #define KVBASE(buf) (base + 16384u + (uint32_t)(buf) * 32768u)

    // issue Q (hi 8KB @0, lo 8KB @8192) + KV stage 0, one commit group
    #pragma unroll
    for (int s = 0; s < 8; s++) {
        int i = tid + s * 128;
        int tl = i >> 9, j = i & 511, row = j >> 3, ch = j & 7;
        uint32_t dst = base + (uint32_t)tl * 8192u + row * 128u + ((ch ^ (row & 7)) * 16);
        const __nv_bfloat16* src = (tl ? Ql_g : Qh_g)
            + (rowBase + q0 + row) * NFEAT + colBase + ch * 8;
        CP_ASYNC16(dst, src);
    }
    #define ISSUE_KV(jt, buf) do { \
        int j0_ = (jt) * 64; \
        _Pragma("unroll") \
        for (int s = 0; s < 16; s++) { \
            int i = tid + s * 128; \
            int tl = i >> 9, j = i & 511, row = j >> 3, ch = j & 7; \
            uint32_t dst = KVBASE(buf) + (uint32_t)tl * 8192u + row * 128u \
                         + ((ch ^ (row & 7)) * 16); \
            size_t off = (rowBase + j0_ + row) * NFEAT + colBase + ch * 8; \
            const __nv_bfloat16* src = (tl == 0 ? Kh_g : tl == 1 ? Kl_g : \
                                        tl == 2 ? Vh_g : Vl_g) + off; \
            CP_ASYNC16(dst, src); \
        } \
        CP_COMMIT(); \
    } while (0)
    ISSUE_KV(0, 0);   // the Q loads above ride in this same group

    float m0 = -INFINITY, m1 = -INFINITY, l0 = 0.f, l1 = 0.f;
    float o[8][4];
    #pragma unroll
    for (int dj = 0; dj < 8; dj++)
        #pragma unroll
        for (int e = 0; e < 4; e++) o[dj][e] = 0.f;

    uint32_t qh[4][4], ql[4][4];
    const float inv_scale = 0.03125f;          // 1/sqrt(1024)

    #pragma unroll 1
    for (int t = 0; t < T; t++) {
        __syncthreads();                       // all warps done reading buf (t+1)&1
        if (t + 1 < T) { ISSUE_KV(t + 1, (t + 1) & 1); CP_WAIT(1); }
        else           { CP_WAIT(0); }
        __syncthreads();                       // stage t (and Q on t=0) ready

        if (t == 0) {
            #pragma unroll
            for (int ks = 0; ks < 4; ks++) {
                int row = wm * 16 + (lane & 15);
                int ch = ks * 2 + (lane >> 4);
                uint32_t sw = (uint32_t)((ch ^ (row & 7)) * 16);
                ldmx4(qh[ks], base + row * 128u + sw);
                ldmx4(ql[ks], base + 8192u + row * 128u + sw);
            }
        }

        const uint32_t kb = KVBASE(t & 1);

        // ---- S = Q K^T (m16 x n64), 3-term split ----
        float s[8][4];
        #pragma unroll
        for (int nj = 0; nj < 8; nj++)
            #pragma unroll
            for (int e = 0; e < 4; e++) s[nj][e] = 0.f;

        #pragma unroll
        for (int ks = 0; ks < 4; ks++) {
            #pragma unroll
            for (int p = 0; p < 4; p++) {
                int row = p * 16 + (lane >> 4) * 8 + (lane & 7);
                int ch = ks * 2 + ((lane >> 3) & 1);
                uint32_t sw = (uint32_t)((ch ^ (row & 7)) * 16);
                uint32_t th[4], tl4[4];
                ldmx4(th,  kb + row * 128u + sw);            // Kh
                ldmx4(tl4, kb + 8192u + row * 128u + sw);    // Kl
                mma16816(s[2*p],   qh[ks], th[0],  th[1]);
                mma16816(s[2*p],   qh[ks], tl4[0], tl4[1]);
                mma16816(s[2*p],   ql[ks], th[0],  th[1]);
                mma16816(s[2*p+1], qh[ks], th[2],  th[3]);
                mma16816(s[2*p+1], qh[ks], tl4[2], tl4[3]);
                mma16816(s[2*p+1], ql[ks], th[2],  th[3]);
            }
        }

        // ---- scale + causal mask + online softmax on fragments ----
        const bool diag = (t == qt);
        const int qrow0 = q0 + wm * 16 + (lane >> 2);
        float mx0 = -INFINITY, mx1 = -INFINITY;
        #pragma unroll
        for (int nj = 0; nj < 8; nj++) {
            #pragma unroll
            for (int e = 0; e < 4; e++) s[nj][e] *= inv_scale;
            if (diag) {
                int kc = t * 64 + nj * 8 + (lane & 3) * 2;
                if (kc     > qrow0)     s[nj][0] = -INFINITY;
                if (kc + 1 > qrow0)     s[nj][1] = -INFINITY;
                if (kc     > qrow0 + 8) s[nj][2] = -INFINITY;
                if (kc + 1 > qrow0 + 8) s[nj][3] = -INFINITY;
            }
            mx0 = fmaxf(mx0, fmaxf(s[nj][0], s[nj][1]));
            mx1 = fmaxf(mx1, fmaxf(s[nj][2], s[nj][3]));
        }
        mx0 = fmaxf(mx0, __shfl_xor_sync(0xffffffffu, mx0, 1));
        mx0 = fmaxf(mx0, __shfl_xor_sync(0xffffffffu, mx0, 2));
        mx1 = fmaxf(mx1, __shfl_xor_sync(0xffffffffu, mx1, 1));
        mx1 = fmaxf(mx1, __shfl_xor_sync(0xffffffffu, mx1, 2));

        float nm0 = fmaxf(m0, mx0), nm1 = fmaxf(m1, mx1);
        float a0 = __expf(m0 - nm0), a1 = __expf(m1 - nm1);
        float rs0 = 0.f, rs1 = 0.f;
        #pragma unroll
        for (int nj = 0; nj < 8; nj++) {
            s[nj][0] = __expf(s[nj][0] - nm0);
            s[nj][1] = __expf(s[nj][1] - nm0);
            s[nj][2] = __expf(s[nj][2] - nm1);
            s[nj][3] = __expf(s[nj][3] - nm1);
            rs0 += s[nj][0] + s[nj][1];
            rs1 += s[nj][2] + s[nj][3];
        }
        rs0 += __shfl_xor_sync(0xffffffffu, rs0, 1);
        rs0 += __shfl_xor_sync(0xffffffffu, rs0, 2);
        rs1 += __shfl_xor_sync(0xffffffffu, rs1, 1);
        rs1 += __shfl_xor_sync(0xffffffffu, rs1, 2);
        l0 = l0 * a0 + rs0; l1 = l1 * a1 + rs1;
        m0 = nm0; m1 = nm1;
        #pragma unroll
        for (int dj = 0; dj < 8; dj++) {
            o[dj][0] *= a0; o[dj][1] *= a0;
            o[dj][2] *= a1; o[dj][3] *= a1;
        }

        // ---- O += P V, P split in registers, V via ldmatrix.trans ----
        #pragma unroll
        for (int kf = 0; kf < 4; kf++) {
            uint32_t ph[4], pl[4];
            split2(s[2*kf][0],   s[2*kf][1],   ph[0], pl[0]);
            split2(s[2*kf][2],   s[2*kf][3],   ph[1], pl[1]);
            split2(s[2*kf+1][0], s[2*kf+1][1], ph[2], pl[2]);
            split2(s[2*kf+1][2], s[2*kf+1][3], ph[3], pl[3]);
            #pragma unroll
            for (int dp = 0; dp < 4; dp++) {
                int row = kf * 16 + ((lane >> 3) & 1) * 8 + (lane & 7);
                int ch = dp * 2 + (lane >> 4);
                uint32_t sw = (uint32_t)((ch ^ (row & 7)) * 16);
                uint32_t vh4[4], vl4[4];
                ldmx4t(vh4, kb + 16384u + row * 128u + sw);  // Vh
                ldmx4t(vl4, kb + 24576u + row * 128u + sw);  // Vl
                mma16816(o[2*dp],   ph, vh4[0], vh4[1]);
                mma16816(o[2*dp],   ph, vl4[0], vl4[1]);
                mma16816(o[2*dp],   pl, vh4[0], vh4[1]);
                mma16816(o[2*dp+1], ph, vh4[2], vh4[3]);
                mma16816(o[2*dp+1], ph, vl4[2], vl4[3]);
                mma16816(o[2*dp+1], pl, vh4[2], vh4[3]);
            }
        }
    }

    // ---- normalize + write hi/lo bf16 ----
    const float i0 = 1.f / l0, i1 = 1.f / l1;
    const int qrow = q0 + wm * 16 + (lane >> 2);
    #pragma unroll
    for (int dj = 0; dj < 8; dj++) {
        int col = colBase + dj * 8 + (lane & 3) * 2;
        size_t off0 = (rowBase + qrow) * NFEAT + col;
        size_t off1 = (rowBase + qrow + 8) * NFEAT + col;
        uint32_t h, l;
        split2(o[dj][0] * i0, o[dj][1] * i0, h, l);
        *(uint32_t*)(Oh + off0) = h; *(uint32_t*)(Ol + off0) = l;
        split2(o[dj][2] * i1, o[dj][3] * i1, h, l);
        *(uint32_t*)(Oh + off1) = h; *(uint32_t*)(Ol + off1) = l;
    }
}

// ---------------------------------------------------------------------------
// Launch
// ---------------------------------------------------------------------------
extern "C" void kernel_launch(void* const* d_in, const int* in_sizes, int n_in,
                              void* d_out, int out_size)
{
    const float* X  = (const float*)d_in[0];
    const float* Wq = (const float*)d_in[1];
    const float* bq = (const float*)d_in[2];
    const float* Wk = (const float*)d_in[3];
    const float* bk = (const float*)d_in[4];
    const float* Wv = (const float*)d_in[5];
    const float* bv = (const float*)d_in[6];
    const float* Wo = (const float*)d_in[7];
    const float* bo = (const float*)d_in[8];
    float* out = (float*)d_out;

    __nv_bfloat16 *Ch, *Cl, *Xh, *Xl, *WqH, *WqL, *WkH, *WkL, *WvH, *WvL, *WoH, *WoL;
    __nv_bfloat16 *XfH, *XfL, *QH, *QL, *KH, *KL, *VH, *VL, *AH, *AL;
    cudaGetSymbolAddress((void**)&Ch,  g_Ch);  cudaGetSymbolAddress((void**)&Cl,  g_Cl);
    cudaGetSymbolAddress((void**)&Xh,  g_Xh);  cudaGetSymbolAddress((void**)&Xl,  g_Xl);
    cudaGetSymbolAddress((void**)&WqH, g_WqH); cudaGetSymbolAddress((void**)&WqL, g_WqL);
    cudaGetSymbolAddress((void**)&WkH, g_WkH); cudaGetSymbolAddress((void**)&WkL, g_WkL);
    cudaGetSymbolAddress((void**)&WvH, g_WvH); cudaGetSymbolAddress((void**)&WvL, g_WvL);
    cudaGetSymbolAddress((void**)&WoH, g_WoH); cudaGetSymbolAddress((void**)&WoL, g_WoL);
    cudaGetSymbolAddress((void**)&XfH, g_XfH); cudaGetSymbolAddress((void**)&XfL, g_XfL);
    cudaGetSymbolAddress((void**)&QH,  g_QH);  cudaGetSymbolAddress((void**)&QL,  g_QL);
    cudaGetSymbolAddress((void**)&KH,  g_KH);  cudaGetSymbolAddress((void**)&KL,  g_KL);
    cudaGetSymbolAddress((void**)&VH,  g_VH);  cudaGetSymbolAddress((void**)&VL,  g_VL);
    cudaGetSymbolAddress((void**)&AH,  g_AH);  cudaGetSymbolAddress((void**)&AL,  g_AL);

    cudaFuncSetAttribute(mma_gemm_kernel,
                         cudaFuncAttributeMaxDynamicSharedMemorySize, GEMM_SMEM);
    cudaFuncSetAttribute(attn_mma_kernel,
                         cudaFuncAttributeMaxDynamicSharedMemorySize, ATTN_SMEM);

    // 1) cosine matrix (bf16 hi/lo)
    gen_cos_kernel<<<(NFEAT * NFEAT) / 256, 256>>>();

    // 2) split inputs to bf16 hi/lo
    split_kernel<<<(MTOT * NFEAT) / 256, 256>>>(X, Xh, Xl, MTOT * NFEAT);
    split_kernel<<<(NFEAT * NFEAT) / 256, 256>>>(Wq, WqH, WqL, NFEAT * NFEAT);
    split_kernel<<<(NFEAT * NFEAT) / 256, 256>>>(Wk, WkH, WkL, NFEAT * NFEAT);
    split_kernel<<<(NFEAT * NFEAT) / 256, 256>>>(Wv, WvH, WvL, NFEAT * NFEAT);
    split_kernel<<<(NFEAT * NFEAT) / 256, 256>>>(Wo, WoH, WoL, NFEAT * NFEAT);

    dim3 gg(NFEAT / 128, MTOT / 128);   // (8, 32)

    // 3) Xf = X @ C (C symmetric) -> hi/lo
    mma_gemm_kernel<<<gg, 256, GEMM_SMEM>>>(Xh, Xl, Ch, Cl,
                                            nullptr, nullptr, XfH, XfL);
    // 4) Q/K/V = Xf @ W^T + b -> hi/lo bf16 (feed attention tensor cores)
    mma_gemm_kernel<<<gg, 256, GEMM_SMEM>>>(XfH, XfL, WqH, WqL, bq, nullptr, QH, QL);
    mma_gemm_kernel<<<gg, 256, GEMM_SMEM>>>(XfH, XfL, WkH, WkL, bk, nullptr, KH, KL);
    mma_gemm_kernel<<<gg, 256, GEMM_SMEM>>>(XfH, XfL, WvH, WvL, bv, nullptr, VH, VL);

    // 5) tensor-core causal attention -> hi/lo
    attn_mma_kernel<<<dim3(L_SEQ / 64, BATCH * NHEAD), 128, ATTN_SMEM>>>(
        QH, QL, KH, KL, VH, VL, AH, AL);

    // 6) out = A @ Wo^T + bo
    mma_gemm_kernel<<<gg, 256, GEMM_SMEM>>>(AH, AL, WoH, WoL, bo, out, nullptr, nullptr);
}

// round 5
// speedup vs baseline: 4.0534x; 1.0790x over previous
#include <cuda_runtime.h>
#include <cuda_bf16.h>
#include <math.h>
#include <stdint.h>

// Problem constants
#define L_SEQ  2048
#define NFEAT  1024
#define NHEAD  16
#define DHEAD  64
#define BATCH  2
#define MTOT   (BATCH * L_SEQ)   // 4096

// ---------------------------------------------------------------------------
// Helpers
// ---------------------------------------------------------------------------
__device__ __forceinline__ uint32_t smem_u32(const void* p) {
    uint32_t a;
    asm("{ .reg .u64 t; cvta.to.shared.u64 t, %1; cvt.u32.u64 %0, t; }" : "=r"(a) : "l"(p));
    return a;
}

#define CP_ASYNC16(dst, src) \
    asm volatile("cp.async.cg.shared.global [%0], [%1], 16;" :: "r"(dst), "l"(src))
#define CP_COMMIT()  asm volatile("cp.async.commit_group;" ::: "memory")
#define CP_WAIT(n)   asm volatile("cp.async.wait_group %0;" :: "n"(n) : "memory")

__device__ __forceinline__ void ldmx4(uint32_t (&r)[4], uint32_t addr) {
    asm volatile("ldmatrix.sync.aligned.m8n8.x4.shared.b16 {%0,%1,%2,%3}, [%4];"
        : "=r"(r[0]), "=r"(r[1]), "=r"(r[2]), "=r"(r[3]) : "r"(addr));
}
__device__ __forceinline__ void ldmx4t(uint32_t (&r)[4], uint32_t addr) {
    asm volatile("ldmatrix.sync.aligned.m8n8.x4.trans.shared.b16 {%0,%1,%2,%3}, [%4];"
        : "=r"(r[0]), "=r"(r[1]), "=r"(r[2]), "=r"(r[3]) : "r"(addr));
}

__device__ __forceinline__ void mma16816(float (&d)[4], const uint32_t (&a)[4],
                                         uint32_t b0, uint32_t b1) {
    asm volatile("mma.sync.aligned.m16n8k16.row.col.f32.bf16.bf16.f32 "
        "{%0,%1,%2,%3}, {%4,%5,%6,%7}, {%8,%9}, {%0,%1,%2,%3};"
        : "+f"(d[0]), "+f"(d[1]), "+f"(d[2]), "+f"(d[3])
        : "r"(a[0]), "r"(a[1]), "r"(a[2]), "r"(a[3]), "r"(b0), "r"(b1));
}

// split (x,y) fp32 pair into packed bf16x2 hi + bf16x2 lo residual
__device__ __forceinline__ void split2(float x, float y, uint32_t& h, uint32_t& l) {
    __nv_bfloat16 hx = __float2bfloat16(x), hy = __float2bfloat16(y);
    __nv_bfloat162 hh; hh.x = hx; hh.y = hy;
    __nv_bfloat162 ll;
    ll.x = __float2bfloat16(x - __bfloat162float(hx));
    ll.y = __float2bfloat16(y - __bfloat162float(hy));
    h = *reinterpret_cast<uint32_t*>(&hh);
    l = *reinterpret_cast<uint32_t*>(&ll);
}

// ---------------------------------------------------------------------------
// Device scratch
// ---------------------------------------------------------------------------
#define NN (NFEAT * NFEAT)
__device__ __nv_bfloat16 g_Ch  [NN],       g_Cl  [NN];        // cosine matrix
__device__ __nv_bfloat16 g_Xh  [MTOT * NFEAT], g_Xl [MTOT * NFEAT];
__device__ __nv_bfloat16 g_WallH[3 * NN],  g_WallL[3 * NN];   // [Wq;Wk;Wv]
__device__ __nv_bfloat16 g_WpH [3 * NN],   g_WpL [3 * NN];    // [Wq;Wk;Wv] @ C
__device__ __nv_bfloat16 g_WoH [NN],       g_WoL [NN];
__device__ __nv_bfloat16 g_QH [MTOT * NFEAT], g_QL [MTOT * NFEAT];
__device__ __nv_bfloat16 g_KH [MTOT * NFEAT], g_KL [MTOT * NFEAT];
__device__ __nv_bfloat16 g_VH [MTOT * NFEAT], g_VL [MTOT * NFEAT];
__device__ __nv_bfloat16 g_AH [MTOT * NFEAT], g_AL [MTOT * NFEAT];

// ---------------------------------------------------------------------------
// C[k][n] = cos(2*pi*k*n/1024)/1024, as bf16 hi/lo split
// ---------------------------------------------------------------------------
__global__ void gen_cos_kernel() {
    int idx = blockIdx.x * blockDim.x + threadIdx.x;
    int k = idx >> 10, n = idx & 1023;
    int kn = (k * n) & 1023;
    float v = cosf((float)kn * 6.135923151542565e-3f) * 9.765625e-4f;
    __nv_bfloat16 h = __float2bfloat16(v);
    g_Ch[idx] = h;
    g_Cl[idx] = __float2bfloat16(v - __bfloat162float(h));
}

// generic fp32 -> hi/lo split
__global__ void split_kernel(const float* __restrict__ in,
                             __nv_bfloat16* __restrict__ hi,
                             __nv_bfloat16* __restrict__ lo, int n) {
    int i = blockIdx.x * blockDim.x + threadIdx.x;
    if (i < n) {
        float x = in[i];
        __nv_bfloat16 h = __float2bfloat16(x);
        hi[i] = h;
        lo[i] = __float2bfloat16(x - __bfloat162float(h));
    }
}

// fused split of Wq,Wk,Wv (-> stacked Wall) and Wo (-> WoH/L), one launch
__global__ void split_weights_kernel(const float* __restrict__ Wq,
                                     const float* __restrict__ Wk,
                                     const float* __restrict__ Wv,
                                     const float* __restrict__ Wo) {
    int idx = blockIdx.x * blockDim.x + threadIdx.x;   // 0 .. 4*NN-1
    int w = idx >> 20;                                  // NN = 2^20
    int i = idx & (NN - 1);
    const float* src = (w == 0) ? Wq : (w == 1) ? Wk : (w == 2) ? Wv : Wo;
    float x = src[i];
    __nv_bfloat16 h = __float2bfloat16(x);
    __nv_bfloat16 l = __float2bfloat16(x - __bfloat162float(h));
    if (w < 3) { g_WallH[w * NN + i] = h; g_WallL[w * NN + i] = l; }
    else       { g_WoH[i] = h;            g_WoL[i] = l; }
}

// ---------------------------------------------------------------------------
// Split-bf16 NT GEMM on mma.sync (HMMA), 3-stage cp.async pipeline.
//   Out[M,1024] = A[M,1024] @ B[1024,1024]^T (+bias), D ~= AhBh + AhBl + AlBh.
//   128x128 tile, BK=32, 8 warps (64x32 each). M = 128 * gridDim.y.
// ---------------------------------------------------------------------------
#define STAGE_BYTES 32768                      // sA 16KB + sB 16KB
#define GEMM_STAGES 3
#define GEMM_SMEM   (GEMM_STAGES * STAGE_BYTES + 128)

__global__ __launch_bounds__(256, 1) void mma_gemm_kernel(
    const __nv_bfloat16* __restrict__ Ah, const __nv_bfloat16* __restrict__ Al,
    const __nv_bfloat16* __restrict__ Bh, const __nv_bfloat16* __restrict__ Bl,
    const float* __restrict__ bias, float* __restrict__ outF,
    __nv_bfloat16* __restrict__ outH, __nv_bfloat16* __restrict__ outL)
{
    extern __shared__ char sraw[];
    uint32_t base = smem_u32(sraw);
    base = (base + 127) & ~127u;

    const int tid  = threadIdx.x;
    const int lane = tid & 31;
    const int wid  = tid >> 5;
    const int wm   = wid & 1;
    const int wn   = wid >> 1;
    const int bx = blockIdx.x, by = blockIdx.y;

    const size_t aBase = (size_t)by * 128 * 1024;
    const size_t bBase = (size_t)bx * 128 * 1024;

    float acc[4][4][4];
    #pragma unroll
    for (int i = 0; i < 4; i++)
        #pragma unroll
        for (int j = 0; j < 4; j++)
            #pragma unroll
            for (int r = 0; r < 4; r++) acc[i][j][r] = 0.f;

    #define ISSUE_STAGE(c) do { \
        const uint32_t sb = base + ((c) % GEMM_STAGES) * STAGE_BYTES; \
        const int k0 = (c) * 32; \
        _Pragma("unroll") \
        for (int s = 0; s < 8; s++) { \
            int i  = tid + s * 256; \
            int tl = i >> 10; \
            int j  = i & 1023; \
            int row = j >> 3; \
            int ch  = j & 7; \
            uint32_t dst = sb + (uint32_t)tl * 16384u + (uint32_t)row * 128u \
                         + (uint32_t)((ch ^ (row & 7)) * 16); \
            size_t off = (size_t)row * 1024 + k0 + (ch & 3) * 8; \
            const __nv_bfloat16* src = (tl == 0) \
                ? ((ch < 4 ? Ah : Al) + aBase + off) \
                : ((ch < 4 ? Bh : Bl) + bBase + off); \
            CP_ASYNC16(dst, src); \
        } \
        CP_COMMIT(); \
    } while (0)

    ISSUE_STAGE(0);
    ISSUE_STAGE(1);

    #pragma unroll 1
    for (int c = 0; c < 32; c++) {
        __syncthreads();
        if (c + 2 < 32) { ISSUE_STAGE(c + 2); CP_WAIT(2); }
        else if (c + 1 < 32) { CP_WAIT(1); }
        else { CP_WAIT(0); }
        __syncthreads();

        const uint32_t sA = base + (c % GEMM_STAGES) * STAGE_BYTES;
        const uint32_t sB = sA + 16384;

        #pragma unroll
        for (int ks = 0; ks < 2; ks++) {
            uint32_t ahf[4][4], alf[4][4], bhf[4][2], blf[4][2];
            #pragma unroll
            for (int mi = 0; mi < 4; mi++) {
                int row = wm * 64 + mi * 16 + (lane & 15);
                int chH = ks * 2 + (lane >> 4);
                int chL = chH + 4;
                ldmx4(ahf[mi], sA + row * 128 + ((chH ^ (row & 7)) * 16));
                ldmx4(alf[mi], sA + row * 128 + ((chL ^ (row & 7)) * 16));
            }
            #pragma unroll
            for (int p = 0; p < 2; p++) {
                int row = wn * 32 + p * 16 + (lane >> 4) * 8 + (lane & 7);
                int chH = ks * 2 + ((lane >> 3) & 1);
                int chL = chH + 4;
                uint32_t th[4], tl4[4];
                ldmx4(th,  sB + row * 128 + ((chH ^ (row & 7)) * 16));
                ldmx4(tl4, sB + row * 128 + ((chL ^ (row & 7)) * 16));
                bhf[2*p][0] = th[0];   bhf[2*p][1] = th[1];
                bhf[2*p+1][0] = th[2]; bhf[2*p+1][1] = th[3];
                blf[2*p][0] = tl4[0];  blf[2*p][1] = tl4[1];
                blf[2*p+1][0] = tl4[2]; blf[2*p+1][1] = tl4[3];
            }
            #pragma unroll
            for (int mi = 0; mi < 4; mi++)
                #pragma unroll
                for (int nj = 0; nj < 4; nj++) {
                    mma16816(acc[mi][nj], ahf[mi], bhf[nj][0], bhf[nj][1]);
                    mma16816(acc[mi][nj], ahf[mi], blf[nj][0], blf[nj][1]);
                    mma16816(acc[mi][nj], alf[mi], bhf[nj][0], bhf[nj][1]);
                }
        }
    }

    const int r0 = by * 128 + wm * 64 + (lane >> 2);
    const int c0 = bx * 128 + wn * 32 + (lane & 3) * 2;
    #pragma unroll
    for (int mi = 0; mi < 4; mi++)
        #pragma unroll
        for (int nj = 0; nj < 4; nj++)
            #pragma unroll
            for (int h = 0; h < 2; h++) {
                int r = r0 + mi * 16 + h * 8;
                int cc = c0 + nj * 8;
                float v0 = acc[mi][nj][2*h+0];
                float v1 = acc[mi][nj][2*h+1];
                if (bias) { v0 += bias[cc]; v1 += bias[cc + 1]; }
                size_t o = (size_t)r * 1024 + cc;
                if (outF) *(float2*)(outF + o) = make_float2(v0, v1);
                if (outH) {
                    uint32_t ph, pl;
                    split2(v0, v1, ph, pl);
                    *(uint32_t*)(outH + o) = ph;
                    *(uint32_t*)(outL + o) = pl;
                }
            }
}

// ---------------------------------------------------------------------------
// Tensor-core causal flash attention, split-bf16 (3-term) QK^T and PV.
// Grid: x = bh (32), y = qt index; qt = 31 - blockIdx.y (longest blocks first).
// ---------------------------------------------------------------------------
#define ATTN_SMEM (16384 + 2 * 32768 + 128)

__global__ __launch_bounds__(128, 2) void attn_mma_kernel(
    const __nv_bfloat16* __restrict__ Qh_g, const __nv_bfloat16* __restrict__ Ql_g,
    const __nv_bfloat16* __restrict__ Kh_g, const __nv_bfloat16* __restrict__ Kl_g,
    const __nv_bfloat16* __restrict__ Vh_g, const __nv_bfloat16* __restrict__ Vl_g,
    __nv_bfloat16* __restrict__ Oh, __nv_bfloat16* __restrict__ Ol)
{
    extern __shared__ char sraw[];
    uint32_t base = smem_u32(sraw);
    base = (base + 127) & ~127u;

    const int tid  = threadIdx.x;
    const int lane = tid & 31;
    const int wm   = tid >> 5;
    const int qt   = 31 - blockIdx.y;          // longest-first scheduling
    const int q0   = qt * 64;
    const int bh   = blockIdx.x;
    const size_t rowBase = (size_t)(bh >> 4) * L_SEQ;
    const int colBase = (bh & 15) * DHEAD;
    const int T = qt + 1;

    #define KVBASE(buf) (base + 16384u + (uint32_t)(buf) * 32768u)

    #pragma unroll
    for (int s = 0; s < 8; s++) {
        int i = tid + s * 128;
        int tl = i >> 9, j = i & 511, row = j >> 3, ch = j & 7;
        uint32_t dst = base + (uint32_t)tl * 8192u + row * 128u + ((ch ^ (row & 7)) * 16);
        const __nv_bfloat16* src = (tl ? Ql_g : Qh_g)
            + (rowBase + q0 + row) * NFEAT + colBase + ch * 8;
        CP_ASYNC16(dst, src);
    }
    #define ISSUE_KV(jt, buf) do { \
        int j0_ = (jt) * 64; \
        _Pragma("unroll") \
        for (int s = 0; s < 16; s++) { \
            int i = tid + s * 128; \
            int tl = i >> 9, j = i & 511, row = j >> 3, ch = j & 7; \
            uint32_t dst = KVBASE(buf) + (uint32_t)tl * 8192u + row * 128u \
                         + ((ch ^ (row & 7)) * 16); \
            size_t off = (rowBase + j0_ + row) * NFEAT + colBase + ch * 8; \
            const __nv_bfloat16* src = (tl == 0 ? Kh_g : tl == 1 ? Kl_g : \
                                        tl == 2 ? Vh_g : Vl_g) + off; \
            CP_ASYNC16(dst, src); \
        } \
        CP_COMMIT(); \
    } while (0)
    ISSUE_KV(0, 0);

    float m0 = -INFINITY, m1 = -INFINITY, l0 = 0.f, l1 = 0.f;
    float o[8][4];
    #pragma unroll
    for (int dj = 0; dj < 8; dj++)
        #pragma unroll
        for (int e = 0; e < 4; e++) o[dj][e] = 0.f;

    uint32_t qh[4][4], ql[4][4];
    const float inv_scale = 0.03125f;

    #pragma unroll 1
    for (int t = 0; t < T; t++) {
        __syncthreads();
        if (t + 1 < T) { ISSUE_KV(t + 1, (t + 1) & 1); CP_WAIT(1); }
        else           { CP_WAIT(0); }
        __syncthreads();

        if (t == 0) {
            #pragma unroll
            for (int ks = 0; ks < 4; ks++) {
                int row = wm * 16 + (lane & 15);
                int ch = ks * 2 + (lane >> 4);
                uint32_t sw = (uint32_t)((ch ^ (row & 7)) * 16);
                ldmx4(qh[ks], base + row * 128u + sw);
                ldmx4(ql[ks], base + 8192u + row * 128u + sw);
            }
        }

        const uint32_t kb = KVBASE(t & 1);

        float s[8][4];
        #pragma unroll
        for (int nj = 0; nj < 8; nj++)
            #pragma unroll
            for (int e = 0; e < 4; e++) s[nj][e] = 0.f;

        #pragma unroll
        for (int ks = 0; ks < 4; ks++) {
            #pragma unroll
            for (int p = 0; p < 4; p++) {
                int row = p * 16 + (lane >> 4) * 8 + (lane & 7);
                int ch = ks * 2 + ((lane >> 3) & 1);
                uint32_t sw = (uint32_t)((ch ^ (row & 7)) * 16);
                uint32_t th[4], tl4[4];
                ldmx4(th,  kb + row * 128u + sw);
                ldmx4(tl4, kb + 8192u + row * 128u + sw);
                mma16816(s[2*p],   qh[ks], th[0],  th[1]);
                mma16816(s[2*p],   qh[ks], tl4[0], tl4[1]);
                mma16816(s[2*p],   ql[ks], th[0],  th[1]);
                mma16816(s[2*p+1], qh[ks], th[2],  th[3]);
                mma16816(s[2*p+1], qh[ks], tl4[2], tl4[3]);
                mma16816(s[2*p+1], ql[ks], th[2],  th[3]);
            }
        }

        const bool diag = (t == qt);
        const int qrow0 = q0 + wm * 16 + (lane >> 2);
        float mx0 = -INFINITY, mx1 = -INFINITY;
        #pragma unroll
        for (int nj = 0; nj < 8; nj++) {
            #pragma unroll
            for (int e = 0; e < 4; e++) s[nj][e] *= inv_scale;
            if (diag) {
                int kc = t * 64 + nj * 8 + (lane & 3) * 2;
                if (kc     > qrow0)     s[nj][0] = -INFINITY;
                if (kc + 1 > qrow0)     s[nj][1] = -INFINITY;
                if (kc     > qrow0 + 8) s[nj][2] = -INFINITY;
                if (kc + 1 > qrow0 + 8) s[nj][3] = -INFINITY;
            }
            mx0 = fmaxf(mx0, fmaxf(s[nj][0], s[nj][1]));
            mx1 = fmaxf(mx1, fmaxf(s[nj][2], s[nj][3]));
        }
        mx0 = fmaxf(mx0, __shfl_xor_sync(0xffffffffu, mx0, 1));
        mx0 = fmaxf(mx0, __shfl_xor_sync(0xffffffffu, mx0, 2));
        mx1 = fmaxf(mx1, __shfl_xor_sync(0xffffffffu, mx1, 1));
        mx1 = fmaxf(mx1, __shfl_xor_sync(0xffffffffu, mx1, 2));

        float nm0 = fmaxf(m0, mx0), nm1 = fmaxf(m1, mx1);
        float a0 = __expf(m0 - nm0), a1 = __expf(m1 - nm1);
        float rs0 = 0.f, rs1 = 0.f;
        #pragma unroll
        for (int nj = 0; nj < 8; nj++) {
            s[nj][0] = __expf(s[nj][0] - nm0);
            s[nj][1] = __expf(s[nj][1] - nm0);
            s[nj][2] = __expf(s[nj][2] - nm1);
            s[nj][3] = __expf(s[nj][3] - nm1);
            rs0 += s[nj][0] + s[nj][1];
            rs1 += s[nj][2] + s[nj][3];
        }
        rs0 += __shfl_xor_sync(0xffffffffu, rs0, 1);
        rs0 += __shfl_xor_sync(0xffffffffu, rs0, 2);
        rs1 += __shfl_xor_sync(0xffffffffu, rs1, 1);
        rs1 += __shfl_xor_sync(0xffffffffu, rs1, 2);
        l0 = l0 * a0 + rs0; l1 = l1 * a1 + rs1;
        m0 = nm0; m1 = nm1;
        #pragma unroll
        for (int dj = 0; dj < 8; dj++) {
            o[dj][0] *= a0; o[dj][1] *= a0;
            o[dj][2] *= a1; o[dj][3] *= a1;
        }

        #pragma unroll
        for (int kf = 0; kf < 4; kf++) {
            uint32_t ph[4], pl[4];
            split2(s[2*kf][0],   s[2*kf][1],   ph[0], pl[0]);
            split2(s[2*kf][2],   s[2*kf][3],   ph[1], pl[1]);
            split2(s[2*kf+1][0], s[2*kf+1][1], ph[2], pl[2]);
            split2(s[2*kf+1][2], s[2*kf+1][3], ph[3], pl[3]);
            #pragma unroll
            for (int dp = 0; dp < 4; dp++) {
                int row = kf * 16 + ((lane >> 3) & 1) * 8 + (lane & 7);
                int ch = dp * 2 + (lane >> 4);
                uint32_t sw = (uint32_t)((ch ^ (row & 7)) * 16);
                uint32_t vh4[4], vl4[4];
                ldmx4t(vh4, kb + 16384u + row * 128u + sw);
                ldmx4t(vl4, kb + 24576u + row * 128u + sw);
                mma16816(o[2*dp],   ph, vh4[0], vh4[1]);
                mma16816(o[2*dp],   ph, vl4[0], vl4[1]);
                mma16816(o[2*dp],   pl, vh4[0], vh4[1]);
                mma16816(o[2*dp+1], ph, vh4[2], vh4[3]);
                mma16816(o[2*dp+1], ph, vl4[2], vl4[3]);
                mma16816(o[2*dp+1], pl, vh4[2], vh4[3]);
            }
        }
    }

    const float i0 = 1.f / l0, i1 = 1.f / l1;
    const int qrow = q0 + wm * 16 + (lane >> 2);
    #pragma unroll
    for (int dj = 0; dj < 8; dj++) {
        int col = colBase + dj * 8 + (lane & 3) * 2;
        size_t off0 = (rowBase + qrow) * NFEAT + col;
        size_t off1 = (rowBase + qrow + 8) * NFEAT + col;
        uint32_t h, l;
        split2(o[dj][0] * i0, o[dj][1] * i0, h, l);
        *(uint32_t*)(Oh + off0) = h; *(uint32_t*)(Ol + off0) = l;
        split2(o[dj][2] * i1, o[dj][3] * i1, h, l);
        *(uint32_t*)(Oh + off1) = h; *(uint32_t*)(Ol + off1) = l;
    }
}

// ---------------------------------------------------------------------------
// Launch
// ---------------------------------------------------------------------------
extern "C" void kernel_launch(void* const* d_in, const int* in_sizes, int n_in,
                              void* d_out, int out_size)
{
    const float* X  = (const float*)d_in[0];
    const float* Wq = (const float*)d_in[1];
    const float* bq = (const float*)d_in[2];
    const float* Wk = (const float*)d_in[3];
    const float* bk = (const float*)d_in[4];
    const float* Wv = (const float*)d_in[5];
    const float* bv = (const float*)d_in[6];
    const float* Wo = (const float*)d_in[7];
    const float* bo = (const float*)d_in[8];
    float* out = (float*)d_out;

    __nv_bfloat16 *Ch, *Cl, *Xh, *Xl, *WallH, *WallL, *WpH, *WpL, *WoH, *WoL;
    __nv_bfloat16 *QH, *QL, *KH, *KL, *VH, *VL, *AH, *AL;
    cudaGetSymbolAddress((void**)&Ch,    g_Ch);    cudaGetSymbolAddress((void**)&Cl,    g_Cl);
    cudaGetSymbolAddress((void**)&Xh,    g_Xh);    cudaGetSymbolAddress((void**)&Xl,    g_Xl);
    cudaGetSymbolAddress((void**)&WallH, g_WallH); cudaGetSymbolAddress((void**)&WallL, g_WallL);
    cudaGetSymbolAddress((void**)&WpH,   g_WpH);   cudaGetSymbolAddress((void**)&WpL,   g_WpL);
    cudaGetSymbolAddress((void**)&WoH,   g_WoH);   cudaGetSymbolAddress((void**)&WoL,   g_WoL);
    cudaGetSymbolAddress((void**)&QH,    g_QH);    cudaGetSymbolAddress((void**)&QL,    g_QL);
    cudaGetSymbolAddress((void**)&KH,    g_KH);    cudaGetSymbolAddress((void**)&KL,    g_KL);
    cudaGetSymbolAddress((void**)&VH,    g_VH);    cudaGetSymbolAddress((void**)&VL,    g_VL);
    cudaGetSymbolAddress((void**)&AH,    g_AH);    cudaGetSymbolAddress((void**)&AL,    g_AL);

    cudaFuncSetAttribute(mma_gemm_kernel,
                         cudaFuncAttributeMaxDynamicSharedMemorySize, GEMM_SMEM);
    cudaFuncSetAttribute(attn_mma_kernel,
                         cudaFuncAttributeMaxDynamicSharedMemorySize, ATTN_SMEM);

    // 1) cosine matrix (bf16 hi/lo)
    gen_cos_kernel<<<NN / 256, 256>>>();

    // 2) splits: X, and all four weights in one launch
    split_kernel<<<(MTOT * NFEAT) / 256, 256>>>(X, Xh, Xl, MTOT * NFEAT);
    split_weights_kernel<<<(4 * NN) / 256, 256>>>(Wq, Wk, Wv, Wo);

    // 3) fold IFFT: W' = [Wq;Wk;Wv] @ C   (M=3072 -> grid (8,24))
    mma_gemm_kernel<<<dim3(8, 24), 256, GEMM_SMEM>>>(
        WallH, WallL, Ch, Cl, nullptr, nullptr, WpH, WpL);

    // 4) Q/K/V = X @ W'^T + b  (grid (8,32) each)
    dim3 gg(NFEAT / 128, MTOT / 128);
    mma_gemm_kernel<<<gg, 256, GEMM_SMEM>>>(Xh, Xl, WpH,          WpL,          bq, nullptr, QH, QL);
    mma_gemm_kernel<<<gg, 256, GEMM_SMEM>>>(Xh, Xl, WpH + NN,     WpL + NN,     bk, nullptr, KH, KL);
    mma_gemm_kernel<<<gg, 256, GEMM_SMEM>>>(Xh, Xl, WpH + 2 * NN, WpL + 2 * NN, bv, nullptr, VH, VL);

    // 5) tensor-core causal attention (longest blocks first)
    attn_mma_kernel<<<dim3(BATCH * NHEAD, L_SEQ / 64), 128, ATTN_SMEM>>>(
        QH, QL, KH, KL, VH, VL, AH, AL);

    // 6) out = A @ Wo^T + bo
    mma_gemm_kernel<<<gg, 256, GEMM_SMEM>>>(AH, AL, WoH, WoL, bo, out, nullptr, nullptr);
}

// round 6
// speedup vs baseline: 4.0559x; 1.0006x over previous
#include <cuda_runtime.h>
#include <cuda_bf16.h>
#include <math.h>
#include <stdint.h>

// Problem constants
#define L_SEQ  2048
#define NFEAT  1024
#define NHEAD  16
#define DHEAD  64
#define BATCH  2
#define MTOT   (BATCH * L_SEQ)   // 4096
#define NN     (NFEAT * NFEAT)
#define MTN    (MTOT * NFEAT)

// ---------------------------------------------------------------------------
// Helpers
// ---------------------------------------------------------------------------
__device__ __forceinline__ uint32_t smem_u32(const void* p) {
    uint32_t a;
    asm("{ .reg .u64 t; cvta.to.shared.u64 t, %1; cvt.u32.u64 %0, t; }" : "=r"(a) : "l"(p));
    return a;
}

#define CP_ASYNC16(dst, src) \
    asm volatile("cp.async.cg.shared.global [%0], [%1], 16;" :: "r"(dst), "l"(src))
#define CP_COMMIT()  asm volatile("cp.async.commit_group;" ::: "memory")
#define CP_WAIT(n)   asm volatile("cp.async.wait_group %0;" :: "n"(n) : "memory")

__device__ __forceinline__ void ldmx4(uint32_t (&r)[4], uint32_t addr) {
    asm volatile("ldmatrix.sync.aligned.m8n8.x4.shared.b16 {%0,%1,%2,%3}, [%4];"
        : "=r"(r[0]), "=r"(r[1]), "=r"(r[2]), "=r"(r[3]) : "r"(addr));
}
__device__ __forceinline__ void ldmx4t(uint32_t (&r)[4], uint32_t addr) {
    asm volatile("ldmatrix.sync.aligned.m8n8.x4.trans.shared.b16 {%0,%1,%2,%3}, [%4];"
        : "=r"(r[0]), "=r"(r[1]), "=r"(r[2]), "=r"(r[3]) : "r"(addr));
}

__device__ __forceinline__ void mma16816(float (&d)[4], const uint32_t (&a)[4],
                                         uint32_t b0, uint32_t b1) {
    asm volatile("mma.sync.aligned.m16n8k16.row.col.f32.bf16.bf16.f32 "
        "{%0,%1,%2,%3}, {%4,%5,%6,%7}, {%8,%9}, {%0,%1,%2,%3};"
        : "+f"(d[0]), "+f"(d[1]), "+f"(d[2]), "+f"(d[3])
        : "r"(a[0]), "r"(a[1]), "r"(a[2]), "r"(a[3]), "r"(b0), "r"(b1));
}

// split (x,y) fp32 pair into packed bf16x2 hi + bf16x2 lo residual
__device__ __forceinline__ void split2(float x, float y, uint32_t& h, uint32_t& l) {
    __nv_bfloat16 hx = __float2bfloat16(x), hy = __float2bfloat16(y);
    __nv_bfloat162 hh; hh.x = hx; hh.y = hy;
    __nv_bfloat162 ll;
    ll.x = __float2bfloat16(x - __bfloat162float(hx));
    ll.y = __float2bfloat16(y - __bfloat162float(hy));
    h = *reinterpret_cast<uint32_t*>(&hh);
    l = *reinterpret_cast<uint32_t*>(&ll);
}

// ---------------------------------------------------------------------------
// Device scratch
// ---------------------------------------------------------------------------
__device__ __nv_bfloat16 g_Ch  [NN],      g_Cl  [NN];       // cosine matrix
__device__ __nv_bfloat16 g_Xh  [MTN],     g_Xl  [MTN];
__device__ __nv_bfloat16 g_WallH[3 * NN], g_WallL[3 * NN];  // [Wq;Wk;Wv]
__device__ __nv_bfloat16 g_WpH [3 * NN],  g_WpL [3 * NN];   // [Wq;Wk;Wv] @ C
__device__ __nv_bfloat16 g_WoH [NN],      g_WoL [NN];
__device__ __nv_bfloat16 g_QKVH[3 * MTN], g_QKVL[3 * MTN];  // stacked Q|K|V
__device__ __nv_bfloat16 g_AH  [MTN],     g_AL  [MTN];
__device__ float g_bqkv[3 * NFEAT];                          // [bq|bk|bv]

// ---------------------------------------------------------------------------
// C[k][n] = cos(2*pi*k*n/1024)/1024, as bf16 hi/lo split
// ---------------------------------------------------------------------------
__global__ void gen_cos_kernel() {
    int idx = blockIdx.x * blockDim.x + threadIdx.x;
    int k = idx >> 10, n = idx & 1023;
    int kn = (k * n) & 1023;
    float v = cosf((float)kn * 6.135923151542565e-3f) * 9.765625e-4f;
    __nv_bfloat16 h = __float2bfloat16(v);
    g_Ch[idx] = h;
    g_Cl[idx] = __float2bfloat16(v - __bfloat162float(h));
}

// generic fp32 -> hi/lo split
__global__ void split_kernel(const float* __restrict__ in,
                             __nv_bfloat16* __restrict__ hi,
                             __nv_bfloat16* __restrict__ lo, int n) {
    int i = blockIdx.x * blockDim.x + threadIdx.x;
    if (i < n) {
        float x = in[i];
        __nv_bfloat16 h = __float2bfloat16(x);
        hi[i] = h;
        lo[i] = __float2bfloat16(x - __bfloat162float(h));
    }
}

// fused split of Wq,Wk,Wv (stacked) + Wo, one launch
__global__ void split_weights_kernel(const float* __restrict__ Wq,
                                     const float* __restrict__ Wk,
                                     const float* __restrict__ Wv,
                                     const float* __restrict__ Wo) {
    int idx = blockIdx.x * blockDim.x + threadIdx.x;   // 0 .. 4*NN-1
    int w = idx >> 20;                                  // NN = 2^20
    int i = idx & (NN - 1);
    const float* src = (w == 0) ? Wq : (w == 1) ? Wk : (w == 2) ? Wv : Wo;
    float x = src[i];
    __nv_bfloat16 h = __float2bfloat16(x);
    __nv_bfloat16 l = __float2bfloat16(x - __bfloat162float(h));
    if (w < 3) { g_WallH[w * NN + i] = h; g_WallL[w * NN + i] = l; }
    else       { g_WoH[i] = h;            g_WoL[i] = l; }
}

// concat [bq|bk|bv] -> g_bqkv
__global__ void bias_concat_kernel(const float* __restrict__ bq,
                                   const float* __restrict__ bk,
                                   const float* __restrict__ bv) {
    int i = blockIdx.x * blockDim.x + threadIdx.x;     // 0..3071
    const float* src = (i < 1024) ? bq : (i < 2048) ? bk : bv;
    g_bqkv[i] = src[i & 1023];
}

// ---------------------------------------------------------------------------
// Split-bf16 NT GEMM on mma.sync (HMMA), 3-stage single-barrier pipeline.
//   Out = A @ B^T (+bias), D ~= AhBh + AhBl + AlBh.
//   128x128 tile, BK=32, 8 warps (64x32 each).
//   Epilogue routes by (bx >> 3) into stacked output matrices (QKV fusion);
//   for plain launches gridDim.x = 8 so mat = 0.
// ---------------------------------------------------------------------------
#define STAGE_BYTES 32768                      // sA 16KB + sB 16KB
#define GEMM_STAGES 3
#define GEMM_SMEM   (GEMM_STAGES * STAGE_BYTES + 128)

__global__ __launch_bounds__(256, 1) void mma_gemm_kernel(
    const __nv_bfloat16* __restrict__ Ah, const __nv_bfloat16* __restrict__ Al,
    const __nv_bfloat16* __restrict__ Bh, const __nv_bfloat16* __restrict__ Bl,
    const float* __restrict__ bias, float* __restrict__ outF,
    __nv_bfloat16* __restrict__ outH, __nv_bfloat16* __restrict__ outL,
    size_t matStride)                           // elems between stacked outputs
{
    extern __shared__ char sraw[];
    uint32_t base = smem_u32(sraw);
    base = (base + 127) & ~127u;

    const int tid  = threadIdx.x;
    const int lane = tid & 31;
    const int wid  = tid >> 5;
    const int wm   = wid & 1;
    const int wn   = wid >> 1;
    const int bx = blockIdx.x, by = blockIdx.y;

    const size_t aBase = (size_t)by * 128 * 1024;
    const size_t bBase = (size_t)bx * 128 * 1024;

    float acc[4][4][4];
    #pragma unroll
    for (int i = 0; i < 4; i++)
        #pragma unroll
        for (int j = 0; j < 4; j++)
            #pragma unroll
            for (int r = 0; r < 4; r++) acc[i][j][r] = 0.f;

    #define ISSUE_STAGE(c) do { \
        const uint32_t sb = base + ((c) % GEMM_STAGES) * STAGE_BYTES; \
        const int k0 = (c) * 32; \
        _Pragma("unroll") \
        for (int s = 0; s < 8; s++) { \
            int i  = tid + s * 256; \
            int tl = i >> 10; \
            int j  = i & 1023; \
            int row = j >> 3; \
            int ch  = j & 7; \
            uint32_t dst = sb + (uint32_t)tl * 16384u + (uint32_t)row * 128u \
                         + (uint32_t)((ch ^ (row & 7)) * 16); \
            size_t off = (size_t)row * 1024 + k0 + (ch & 3) * 8; \
            const __nv_bfloat16* src = (tl == 0) \
                ? ((ch < 4 ? Ah : Al) + aBase + off) \
                : ((ch < 4 ? Bh : Bl) + bBase + off); \
            CP_ASYNC16(dst, src); \
        } \
        CP_COMMIT(); \
    } while (0)

    ISSUE_STAGE(0);
    ISSUE_STAGE(1);

    #pragma unroll 1
    for (int c = 0; c < 32; c++) {
        // stage c complete (own groups), then make all threads' writes visible
        if (c < 31) { CP_WAIT(1); } else { CP_WAIT(0); }
        __syncthreads();
        // safe to overwrite buffer (c+2)%3 == (c-1)%3: every thread finished
        // its stage-(c-1) reads before this barrier (they happened last iter)
        if (c + 2 < 32) ISSUE_STAGE(c + 2);

        const uint32_t sA = base + (c % GEMM_STAGES) * STAGE_BYTES;
        const uint32_t sB = sA + 16384;

        #pragma unroll
        for (int ks = 0; ks < 2; ks++) {
            uint32_t ahf[4][4], alf[4][4], bhf[4][2], blf[4][2];
            #pragma unroll
            for (int mi = 0; mi < 4; mi++) {
                int row = wm * 64 + mi * 16 + (lane & 15);
                int chH = ks * 2 + (lane >> 4);
                int chL = chH + 4;
                ldmx4(ahf[mi], sA + row * 128 + ((chH ^ (row & 7)) * 16));
                ldmx4(alf[mi], sA + row * 128 + ((chL ^ (row & 7)) * 16));
            }
            #pragma unroll
            for (int p = 0; p < 2; p++) {
                int row = wn * 32 + p * 16 + (lane >> 4) * 8 + (lane & 7);
                int chH = ks * 2 + ((lane >> 3) & 1);
                int chL = chH + 4;
                uint32_t th[4], tl4[4];
                ldmx4(th,  sB + row * 128 + ((chH ^ (row & 7)) * 16));
                ldmx4(tl4, sB + row * 128 + ((chL ^ (row & 7)) * 16));
                bhf[2*p][0] = th[0];   bhf[2*p][1] = th[1];
                bhf[2*p+1][0] = th[2]; bhf[2*p+1][1] = th[3];
                blf[2*p][0] = tl4[0];  blf[2*p][1] = tl4[1];
                blf[2*p+1][0] = tl4[2]; blf[2*p+1][1] = tl4[3];
            }
            #pragma unroll
            for (int mi = 0; mi < 4; mi++)
                #pragma unroll
                for (int nj = 0; nj < 4; nj++) {
                    mma16816(acc[mi][nj], ahf[mi], bhf[nj][0], bhf[nj][1]);
                    mma16816(acc[mi][nj], ahf[mi], blf[nj][0], blf[nj][1]);
                    mma16816(acc[mi][nj], alf[mi], bhf[nj][0], bhf[nj][1]);
                }
        }
    }

    // epilogue: route by mat = bx >> 3 into stacked outputs
    const int mat = bx >> 3;
    const size_t matOff = (size_t)mat * matStride;
    const int r0 = by * 128 + wm * 64 + (lane >> 2);
    const int cloc0 = (bx & 7) * 128 + wn * 32 + (lane & 3) * 2;
    const int cb0 = bx * 128 + wn * 32 + (lane & 3) * 2;
    #pragma unroll
    for (int mi = 0; mi < 4; mi++)
        #pragma unroll
        for (int nj = 0; nj < 4; nj++)
            #pragma unroll
            for (int h = 0; h < 2; h++) {
                int r = r0 + mi * 16 + h * 8;
                float v0 = acc[mi][nj][2*h+0];
                float v1 = acc[mi][nj][2*h+1];
                if (bias) {
                    v0 += bias[cb0 + nj * 8];
                    v1 += bias[cb0 + nj * 8 + 1];
                }
                size_t o = matOff + (size_t)r * 1024 + cloc0 + nj * 8;
                if (outF) *(float2*)(outF + o) = make_float2(v0, v1);
                if (outH) {
                    uint32_t ph, pl;
                    split2(v0, v1, ph, pl);
                    *(uint32_t*)(outH + o) = ph;
                    *(uint32_t*)(outL + o) = pl;
                }
            }
}

// ---------------------------------------------------------------------------
// Tensor-core causal flash attention, split-bf16 (3-term) QK^T and PV.
// Grid: x = bh (32), y = qt index; qt = 31 - blockIdx.y (longest blocks first).
// ---------------------------------------------------------------------------
#define ATTN_SMEM (16384 + 2 * 32768 + 128)

__global__ __launch_bounds__(128, 2) void attn_mma_kernel(
    const __nv_bfloat16* __restrict__ Qh_g, const __nv_bfloat16* __restrict__ Ql_g,
    const __nv_bfloat16* __restrict__ Kh_g, const __nv_bfloat16* __restrict__ Kl_g,
    const __nv_bfloat16* __restrict__ Vh_g, const __nv_bfloat16* __restrict__ Vl_g,
    __nv_bfloat16* __restrict__ Oh, __nv_bfloat16* __restrict__ Ol)
{
    extern __shared__ char sraw[];
    uint32_t base = smem_u32(sraw);
    base = (base + 127) & ~127u;

    const int tid  = threadIdx.x;
    const int lane = tid & 31;
    const int wm   = tid >> 5;
    const int qt   = 31 - blockIdx.y;          // longest-first scheduling
    const int q0   = qt * 64;
    const int bh   = blockIdx.x;
    const size_t rowBase = (size_t)(bh >> 4) * L_SEQ;
    const int colBase = (bh & 15) * DHEAD;
    const int T = qt + 1;

    #define KVBASE(buf) (base + 16384u + (uint32_t)(buf) * 32768u)

    #pragma unroll
    for (int s = 0; s < 8; s++) {
        int i = tid + s * 128;
        int tl = i >> 9, j = i & 511, row = j >> 3, ch = j & 7;
        uint32_t dst = base + (uint32_t)tl * 8192u + row * 128u + ((ch ^ (row & 7)) * 16);
        const __nv_bfloat16* src = (tl ? Ql_g : Qh_g)
            + (rowBase + q0 + row) * NFEAT + colBase + ch * 8;
        CP_ASYNC16(dst, src);
    }
    #define ISSUE_KV(jt, buf) do { \
        int j0_ = (jt) * 64; \
        _Pragma("unroll") \
        for (int s = 0; s < 16; s++) { \
            int i = tid + s * 128; \
            int tl = i >> 9, j = i & 511, row = j >> 3, ch = j & 7; \
            uint32_t dst = KVBASE(buf) + (uint32_t)tl * 8192u + row * 128u \
                         + ((ch ^ (row & 7)) * 16); \
            size_t off = (rowBase + j0_ + row) * NFEAT + colBase + ch * 8; \
            const __nv_bfloat16* src = (tl == 0 ? Kh_g : tl == 1 ? Kl_g : \
                                        tl == 2 ? Vh_g : Vl_g) + off; \
            CP_ASYNC16(dst, src); \
        } \
        CP_COMMIT(); \
    } while (0)
    ISSUE_KV(0, 0);

    float m0 = -INFINITY, m1 = -INFINITY, l0 = 0.f, l1 = 0.f;
    float o[8][4];
    #pragma unroll
    for (int dj = 0; dj < 8; dj++)
        #pragma unroll
        for (int e = 0; e < 4; e++) o[dj][e] = 0.f;

    uint32_t qh[4][4], ql[4][4];
    const float inv_scale = 0.03125f;

    #pragma unroll 1
    for (int t = 0; t < T; t++) {
        __syncthreads();
        if (t + 1 < T) { ISSUE_KV(t + 1, (t + 1) & 1); CP_WAIT(1); }
        else           { CP_WAIT(0); }
        __syncthreads();

        if (t == 0) {
            #pragma unroll
            for (int ks = 0; ks < 4; ks++) {
                int row = wm * 16 + (lane & 15);
                int ch = ks * 2 + (lane >> 4);
                uint32_t sw = (uint32_t)((ch ^ (row & 7)) * 16);
                ldmx4(qh[ks], base + row * 128u + sw);
                ldmx4(ql[ks], base + 8192u + row * 128u + sw);
            }
        }

        const uint32_t kb = KVBASE(t & 1);

        float s[8][4];
        #pragma unroll
        for (int nj = 0; nj < 8; nj++)
            #pragma unroll
            for (int e = 0; e < 4; e++) s[nj][e] = 0.f;

        #pragma unroll
        for (int ks = 0; ks < 4; ks++) {
            #pragma unroll
            for (int p = 0; p < 4; p++) {
                int row = p * 16 + (lane >> 4) * 8 + (lane & 7);
                int ch = ks * 2 + ((lane >> 3) & 1);
                uint32_t sw = (uint32_t)((ch ^ (row & 7)) * 16);
                uint32_t th[4], tl4[4];
                ldmx4(th,  kb + row * 128u + sw);
                ldmx4(tl4, kb + 8192u + row * 128u + sw);
                mma16816(s[2*p],   qh[ks], th[0],  th[1]);
                mma16816(s[2*p],   qh[ks], tl4[0], tl4[1]);
                mma16816(s[2*p],   ql[ks], th[0],  th[1]);
                mma16816(s[2*p+1], qh[ks], th[2],  th[3]);
                mma16816(s[2*p+1], qh[ks], tl4[2], tl4[3]);
                mma16816(s[2*p+1], ql[ks], th[2],  th[3]);
            }
        }

        const bool diag = (t == qt);
        const int qrow0 = q0 + wm * 16 + (lane >> 2);
        float mx0 = -INFINITY, mx1 = -INFINITY;
        #pragma unroll
        for (int nj = 0; nj < 8; nj++) {
            #pragma unroll
            for (int e = 0; e < 4; e++) s[nj][e] *= inv_scale;
            if (diag) {
                int kc = t * 64 + nj * 8 + (lane & 3) * 2;
                if (kc     > qrow0)     s[nj][0] = -INFINITY;
                if (kc + 1 > qrow0)     s[nj][1] = -INFINITY;
                if (kc     > qrow0 + 8) s[nj][2] = -INFINITY;
                if (kc + 1 > qrow0 + 8) s[nj][3] = -INFINITY;
            }
            mx0 = fmaxf(mx0, fmaxf(s[nj][0], s[nj][1]));
            mx1 = fmaxf(mx1, fmaxf(s[nj][2], s[nj][3]));
        }
        mx0 = fmaxf(mx0, __shfl_xor_sync(0xffffffffu, mx0, 1));
        mx0 = fmaxf(mx0, __shfl_xor_sync(0xffffffffu, mx0, 2));
        mx1 = fmaxf(mx1, __shfl_xor_sync(0xffffffffu, mx1, 1));
        mx1 = fmaxf(mx1, __shfl_xor_sync(0xffffffffu, mx1, 2));

        float nm0 = fmaxf(m0, mx0), nm1 = fmaxf(m1, mx1);
        float a0 = __expf(m0 - nm0), a1 = __expf(m1 - nm1);
        float rs0 = 0.f, rs1 = 0.f;
        #pragma unroll
        for (int nj = 0; nj < 8; nj++) {
            s[nj][0] = __expf(s[nj][0] - nm0);
            s[nj][1] = __expf(s[nj][1] - nm0);
            s[nj][2] = __expf(s[nj][2] - nm1);
            s[nj][3] = __expf(s[nj][3] - nm1);
            rs0 += s[nj][0] + s[nj][1];
            rs1 += s[nj][2] + s[nj][3];
        }
        rs0 += __shfl_xor_sync(0xffffffffu, rs0, 1);
        rs0 += __shfl_xor_sync(0xffffffffu, rs0, 2);
        rs1 += __shfl_xor_sync(0xffffffffu, rs1, 1);
        rs1 += __shfl_xor_sync(0xffffffffu, rs1, 2);
        l0 = l0 * a0 + rs0; l1 = l1 * a1 + rs1;
        m0 = nm0; m1 = nm1;
        #pragma unroll
        for (int dj = 0; dj < 8; dj++) {
            o[dj][0] *= a0; o[dj][1] *= a0;
            o[dj][2] *= a1; o[dj][3] *= a1;
        }

        #pragma unroll
        for (int kf = 0; kf < 4; kf++) {
            uint32_t ph[4], pl[4];
            split2(s[2*kf][0],   s[2*kf][1],   ph[0], pl[0]);
            split2(s[2*kf][2],   s[2*kf][3],   ph[1], pl[1]);
            split2(s[2*kf+1][0], s[2*kf+1][1], ph[2], pl[2]);
            split2(s[2*kf+1][2], s[2*kf+1][3], ph[3], pl[3]);
            #pragma unroll
            for (int dp = 0; dp < 4; dp++) {
                int row = kf * 16 + ((lane >> 3) & 1) * 8 + (lane & 7);
                int ch = dp * 2 + (lane >> 4);
                uint32_t sw = (uint32_t)((ch ^ (row & 7)) * 16);
                uint32_t vh4[4], vl4[4];
                ldmx4t(vh4, kb + 16384u + row * 128u + sw);
                ldmx4t(vl4, kb + 24576u + row * 128u + sw);
                mma16816(o[2*dp],   ph, vh4[0], vh4[1]);
                mma16816(o[2*dp],   ph, vl4[0], vl4[1]);
                mma16816(o[2*dp],   pl, vh4[0], vh4[1]);
                mma16816(o[2*dp+1], ph, vh4[2], vh4[3]);
                mma16816(o[2*dp+1], ph, vl4[2], vl4[3]);
                mma16816(o[2*dp+1], pl, vh4[2], vh4[3]);
            }
        }
    }

    const float i0 = 1.f / l0, i1 = 1.f / l1;
    const int qrow = q0 + wm * 16 + (lane >> 2);
    #pragma unroll
    for (int dj = 0; dj < 8; dj++) {
        int col = colBase + dj * 8 + (lane & 3) * 2;
        size_t off0 = (rowBase + qrow) * NFEAT + col;
        size_t off1 = (rowBase + qrow + 8) * NFEAT + col;
        uint32_t h, l;
        split2(o[dj][0] * i0, o[dj][1] * i0, h, l);
        *(uint32_t*)(Oh + off0) = h; *(uint32_t*)(Ol + off0) = l;
        split2(o[dj][2] * i1, o[dj][3] * i1, h, l);
        *(uint32_t*)(Oh + off1) = h; *(uint32_t*)(Ol + off1) = l;
    }
}

// ---------------------------------------------------------------------------
// Launch
// ---------------------------------------------------------------------------
extern "C" void kernel_launch(void* const* d_in, const int* in_sizes, int n_in,
                              void* d_out, int out_size)
{
    const float* X  = (const float*)d_in[0];
    const float* Wq = (const float*)d_in[1];
    const float* bq = (const float*)d_in[2];
    const float* Wk = (const float*)d_in[3];
    const float* bk = (const float*)d_in[4];
    const float* Wv = (const float*)d_in[5];
    const float* bv = (const float*)d_in[6];
    const float* Wo = (const float*)d_in[7];
    const float* bo = (const float*)d_in[8];
    float* out = (float*)d_out;

    __nv_bfloat16 *Ch, *Cl, *Xh, *Xl, *WallH, *WallL, *WpH, *WpL, *WoH, *WoL;
    __nv_bfloat16 *QKVH, *QKVL, *AH, *AL;
    float* bqkv;
    cudaGetSymbolAddress((void**)&Ch,    g_Ch);    cudaGetSymbolAddress((void**)&Cl,    g_Cl);
    cudaGetSymbolAddress((void**)&Xh,    g_Xh);    cudaGetSymbolAddress((void**)&Xl,    g_Xl);
    cudaGetSymbolAddress((void**)&WallH, g_WallH); cudaGetSymbolAddress((void**)&WallL, g_WallL);
    cudaGetSymbolAddress((void**)&WpH,   g_WpH);   cudaGetSymbolAddress((void**)&WpL,   g_WpL);
    cudaGetSymbolAddress((void**)&WoH,   g_WoH);   cudaGetSymbolAddress((void**)&WoL,   g_WoL);
    cudaGetSymbolAddress((void**)&QKVH,  g_QKVH);  cudaGetSymbolAddress((void**)&QKVL,  g_QKVL);
    cudaGetSymbolAddress((void**)&AH,    g_AH);    cudaGetSymbolAddress((void**)&AL,    g_AL);
    cudaGetSymbolAddress((void**)&bqkv,  g_bqkv);

    cudaFuncSetAttribute(mma_gemm_kernel,
                         cudaFuncAttributeMaxDynamicSharedMemorySize, GEMM_SMEM);
    cudaFuncSetAttribute(attn_mma_kernel,
                         cudaFuncAttributeMaxDynamicSharedMemorySize, ATTN_SMEM);

    // 1) cosine matrix (bf16 hi/lo)
    gen_cos_kernel<<<NN / 256, 256>>>();

    // 2) splits + combined bias
    split_kernel<<<MTN / 256, 256>>>(X, Xh, Xl, MTN);
    split_weights_kernel<<<(4 * NN) / 256, 256>>>(Wq, Wk, Wv, Wo);
    bias_concat_kernel<<<12, 256>>>(bq, bk, bv);

    // 3) fold IFFT: W' = [Wq;Wk;Wv] @ C   (M=3072 -> grid (8,24))
    mma_gemm_kernel<<<dim3(8, 24), 256, GEMM_SMEM>>>(
        WallH, WallL, Ch, Cl, nullptr, nullptr, WpH, WpL, 0);

    // 4) fused QKV: [Q|K|V] = X @ W'^T + bqkv  (grid (24,32) = 768 CTAs)
    mma_gemm_kernel<<<dim3(24, 32), 256, GEMM_SMEM>>>(
        Xh, Xl, WpH, WpL, bqkv, nullptr, QKVH, QKVL, (size_t)MTN);

    // 5) tensor-core causal attention (longest blocks first)
    attn_mma_kernel<<<dim3(BATCH * NHEAD, L_SEQ / 64), 128, ATTN_SMEM>>>(
        QKVH, QKVL, QKVH + MTN, QKVL + MTN, QKVH + 2 * (size_t)MTN, QKVL + 2 * (size_t)MTN,
        AH, AL);

    // 6) out = A @ Wo^T + bo
    mma_gemm_kernel<<<dim3(8, 32), 256, GEMM_SMEM>>>(
        AH, AL, WoH, WoL, bo, out, nullptr, nullptr, 0);
}